// round 5
// baseline (speedup 1.0000x reference)
#include <cuda_runtime.h>
#include <math.h>

#define NPIX 4096

// ---------------- scratch (device globals; allocation is forbidden) ----------------
__device__ __align__(128) float g_skip_u[4 * 64 * NPIX];
__device__ __align__(128) float g_mean  [4 * NPIX];
__device__ __align__(128) float g_thick [4 * NPIX];
__device__ __align__(128) float g_edge  [4 * 64 * NPIX];
__device__ __align__(128) float g_off   [4 * 18 * NPIX];
__device__ __align__(128) float g_d     [4 * 64 * NPIX];
__device__ __align__(128) float g_qkv   [4 * 96 * NPIX];
__device__ __align__(128) float g_av    [4 * 32 * NPIX];
__device__ __align__(128) float g_x2    [4 * 256 * NPIX];
__device__ __align__(128) float g_e     [4 * 64 * NPIX];
__device__ __align__(128) float g_h     [4 * 64 * NPIX];
__device__ __align__(128) float g_h1    [4 * 256 * NPIX];
__device__ __align__(128) float g_h2    [4 * 256 * NPIX];
__device__ __align__(128) float g_t     [4 * 64 * NPIX];
// transposed weights [IC][OC]
__device__ __align__(128) float g_qkvWT [256 * 96];
__device__ __align__(128) float g_projWT[32 * 256];
__device__ __align__(128) float g_downWT[320 * 64];
__device__ __align__(128) float g_mlp1WT[64 * 256];
__device__ __align__(128) float g_mlp2WT[256 * 64];
__device__ __align__(128) float g_upWT  [64 * 256];
__device__ __align__(128) float g_dwT   [9 * 64 * 64];   // deform_w as [k][c][o]

// ---------------- prep: transpose weights ----------------
__global__ void prep_kernel(const float* __restrict__ qkv_w, const float* __restrict__ proj_w,
                            const float* __restrict__ down_w, const float* __restrict__ mlp1_w,
                            const float* __restrict__ mlp2_w, const float* __restrict__ up_w,
                            const float* __restrict__ deform_w) {
    int t0 = blockIdx.x * blockDim.x + threadIdx.x;
    int stride = gridDim.x * blockDim.x;
    for (int i = t0; i < 256 * 96; i += stride) { int ic = i / 96,  oc = i % 96;  g_qkvWT[i]  = qkv_w[oc * 256 + ic]; }
    for (int i = t0; i < 32 * 256; i += stride) { int ic = i / 256, oc = i % 256; g_projWT[i] = proj_w[oc * 32 + ic]; }
    for (int i = t0; i < 320 * 64; i += stride) { int ic = i / 64,  oc = i % 64;  g_downWT[i] = down_w[oc * 320 + ic]; }
    for (int i = t0; i < 64 * 256; i += stride) { int ic = i / 256, oc = i % 256; g_mlp1WT[i] = mlp1_w[oc * 64 + ic]; }
    for (int i = t0; i < 256 * 64; i += stride) { int ic = i / 64,  oc = i % 64;  g_mlp2WT[i] = mlp2_w[oc * 256 + ic]; }
    for (int i = t0; i < 64 * 256; i += stride) { int ic = i / 256, oc = i % 256; g_upWT[i]   = up_w[oc * 64 + ic]; }
    for (int i = t0; i < 9 * 64 * 64; i += stride) {
        int k = i >> 12, c = (i >> 6) & 63, o = i & 63;
        g_dwT[i] = deform_w[(o * 64 + c) * 9 + k];
    }
}

// ---------------- bilinear upsample (half-pixel) + channel mean + thick ----------------
__global__ void upsample_kernel(const float* __restrict__ skip, const float* __restrict__ thick_w,
                                const float* __restrict__ thick_b) {
    int b = blockIdx.y, y = blockIdx.x, x = threadIdx.x;
    float sy = fminf(fmaxf(0.5f * y - 0.25f, 0.f), 31.f);
    float sx = fminf(fmaxf(0.5f * x - 0.25f, 0.f), 31.f);
    int y0 = (int)sy, x0 = (int)sx;
    int y1 = min(y0 + 1, 31), x1 = min(x0 + 1, 31);
    float wy = sy - (float)y0, wx = sx - (float)x0;
    float w00 = (1.f - wy) * (1.f - wx), w01 = (1.f - wy) * wx;
    float w10 = wy * (1.f - wx),         w11 = wy * wx;
    const float* sp = skip + (size_t)b * 64 * 1024;
    float* up = g_skip_u + (size_t)b * 64 * NPIX + y * 64 + x;
    float sum = 0.f, tsum = 0.f;
    for (int c = 0; c < 64; c++) {
        const float* p = sp + c * 1024;
        float v = w00 * p[y0 * 32 + x0] + w01 * p[y0 * 32 + x1]
                + w10 * p[y1 * 32 + x0] + w11 * p[y1 * 32 + x1];
        up[(size_t)c * NPIX] = v;
        sum += v;
        tsum += v * thick_w[c];
    }
    int pix = b * NPIX + y * 64 + x;
    g_mean[pix] = sum * (1.f / 64.f);
    g_thick[pix] = 1.f / (1.f + expf(-(tsum + thick_b[0])));
}

// ---------------- edge conv: 3x3, 1 -> 64 ch, zero pad, no bias ----------------
__global__ void edge_kernel(const float* __restrict__ edge_w) {
    int idx = blockIdx.x * 256 + threadIdx.x;          // 4*64*4096
    int n = idx & 4095, oc = (idx >> 12) & 63, b = idx >> 18;
    int y = n >> 6, x = n & 63;
    const float* mp = g_mean + b * NPIX;
    float a = 0.f;
#pragma unroll
    for (int ky = 0; ky < 3; ky++) {
        int yy = y + ky - 1;
        if (yy < 0 || yy >= 64) continue;
#pragma unroll
        for (int kx = 0; kx < 3; kx++) {
            int xx = x + kx - 1;
            if (xx < 0 || xx >= 64) continue;
            a += mp[yy * 64 + xx] * edge_w[oc * 9 + ky * 3 + kx];
        }
    }
    g_edge[idx] = a;
}

// ---------------- offset conv: 3x3, 64 -> 18, * (1 + 16*thick) ----------------
__global__ __launch_bounds__(128) void off_kernel(const float* __restrict__ off_w,
                                                  const float* __restrict__ off_b) {
    __shared__ float ws[64 * 9 * 18];                  // [c][k][o]
    for (int i = threadIdx.x; i < 64 * 9 * 18; i += 128) {
        int o = i % 18, ck = i / 18;
        ws[i] = off_w[o * 576 + ck];
    }
    __syncthreads();
    int pix = blockIdx.x * 128 + threadIdx.x;          // 16384
    int b = pix >> 12, n = pix & 4095;
    int y = n >> 6, x = n & 63;
    float acc[18];
#pragma unroll
    for (int o = 0; o < 18; o++) acc[o] = 0.f;
    const float* ep = g_edge + (size_t)b * 64 * NPIX;
    for (int ky = 0; ky < 3; ky++) {
        int yy = y + ky - 1;
        if (yy < 0 || yy >= 64) continue;
        for (int kx = 0; kx < 3; kx++) {
            int xx = x + kx - 1;
            if (xx < 0 || xx >= 64) continue;
            int k = ky * 3 + kx;
            const float* col = ep + yy * 64 + xx;
            for (int c = 0; c < 64; c++) {
                float v = col[(size_t)c * NPIX];
                const float* wr = &ws[(c * 9 + k) * 18];
#pragma unroll
                for (int o = 0; o < 18; o++) acc[o] += v * wr[o];
            }
        }
    }
    float tscale = 1.f + 16.f * g_thick[pix];
    float* op = g_off + (size_t)b * 18 * NPIX + n;
#pragma unroll
    for (int o = 0; o < 18; o++) op[(size_t)o * NPIX] = (acc[o] + off_b[o]) * tscale;
}

// ---------------- deformable conv 3x3 (DCNv1) + bias + edge ----------------
__global__ __launch_bounds__(128) void deform_kernel(const float* __restrict__ deform_b) {
    __shared__ float ws[4096];                         // [c][o] for current tap
    int pix = blockIdx.x * 128 + threadIdx.x;          // 16384
    int b = pix >> 12, n = pix & 4095;
    int y = n >> 6, x = n & 63;
    float acc[64];
#pragma unroll
    for (int o = 0; o < 64; o++) acc[o] = 0.f;
    const float* su = g_skip_u + (size_t)b * 64 * NPIX;
    const float* offp = g_off + (size_t)b * 18 * NPIX + n;
    for (int k = 0; k < 9; k++) {
        __syncthreads();
        for (int i = threadIdx.x; i < 4096; i += 128) ws[i] = g_dwT[k * 4096 + i];
        __syncthreads();
        float py = (float)(y + k / 3 - 1) + offp[(size_t)(2 * k) * NPIX];
        float px = (float)(x + k % 3 - 1) + offp[(size_t)(2 * k + 1) * NPIX];
        float y0f = floorf(py), x0f = floorf(px);
        float wy = py - y0f, wx = px - x0f;
        int y0 = (int)y0f, x0 = (int)x0f;
        int y1 = y0 + 1, x1 = x0 + 1;
        bool vy0 = (y0 >= 0 && y0 < 64), vy1 = (y1 >= 0 && y1 < 64);
        bool vx0 = (x0 >= 0 && x0 < 64), vx1 = (x1 >= 0 && x1 < 64);
        float w00 = (vy0 && vx0) ? (1.f - wy) * (1.f - wx) : 0.f;
        float w01 = (vy0 && vx1) ? (1.f - wy) * wx : 0.f;
        float w10 = (vy1 && vx0) ? wy * (1.f - wx) : 0.f;
        float w11 = (vy1 && vx1) ? wy * wx : 0.f;
        int yc0 = min(max(y0, 0), 63), yc1 = min(max(y1, 0), 63);
        int xc0 = min(max(x0, 0), 63), xc1 = min(max(x1, 0), 63);
        const float* p00 = su + yc0 * 64 + xc0;
        const float* p01 = su + yc0 * 64 + xc1;
        const float* p10 = su + yc1 * 64 + xc0;
        const float* p11 = su + yc1 * 64 + xc1;
        for (int c = 0; c < 64; c++) {
            size_t co = (size_t)c * NPIX;
            float val = w00 * p00[co] + w01 * p01[co] + w10 * p10[co] + w11 * p11[co];
            const float4* wr = (const float4*)&ws[c * 64];
#pragma unroll
            for (int o4 = 0; o4 < 16; o4++) {
                float4 w4 = wr[o4];
                acc[o4 * 4 + 0] += val * w4.x;
                acc[o4 * 4 + 1] += val * w4.y;
                acc[o4 * 4 + 2] += val * w4.z;
                acc[o4 * 4 + 3] += val * w4.w;
            }
        }
    }
    const float* ep = g_edge + (size_t)b * 64 * NPIX + n;
    float* dp = g_d + (size_t)b * 64 * NPIX + n;
#pragma unroll
    for (int o = 0; o < 64; o++) dp[(size_t)o * NPIX] = acc[o] + deform_b[o] + ep[(size_t)o * NPIX];
}

// ---------------- generic 1x1-conv GEMM: out[b,oc,n] = sum_ic WT[ic][oc]*in[b,ic,n] ----------------
// act: 0=none, 1=exact GELU.  res: optional residual (same layout as out).
__global__ __launch_bounds__(256) void gemm1x1(const float* __restrict__ inA, int icA,
                                               const float* __restrict__ inB, int IC,
                                               const float* __restrict__ WT,
                                               const float* __restrict__ bias, int OC,
                                               const float* __restrict__ res,
                                               float* __restrict__ out, int act) {
    __shared__ float As[16][64];
    __shared__ float Bs[16][64];
    int tid = threadIdx.x;
    int tx = tid & 15, ty = tid >> 4;
    int n0 = blockIdx.x * 64;
    int oc0 = blockIdx.y * 64;
    float c[4][4] = {};
    int fidx = tid * 4;
    int lkk = fidx >> 6, lcol = fidx & 63;
    int gj = n0 + lcol;
    int lb = gj >> 12, ln = gj & 4095;
    int icB = IC - icA;
    for (int k0 = 0; k0 < IC; k0 += 16) {
        int ic = k0 + lkk;
        const float* src;
        if (ic < icA) src = inA + ((size_t)lb * icA + ic) * NPIX + ln;
        else          src = inB + ((size_t)lb * icB + (ic - icA)) * NPIX + ln;
        *(float4*)&As[lkk][lcol] = *(const float4*)src;
        float4 wv = make_float4(0.f, 0.f, 0.f, 0.f);
        if (oc0 + lcol < OC) wv = *(const float4*)&WT[(size_t)ic * OC + oc0 + lcol];
        *(float4*)&Bs[lkk][lcol] = wv;
        __syncthreads();
#pragma unroll
        for (int k = 0; k < 16; k++) {
            float4 a4 = *(float4*)&As[k][tx * 4];
            float4 b4 = *(float4*)&Bs[k][ty * 4];
            float av_[4] = {a4.x, a4.y, a4.z, a4.w};
            float bv_[4] = {b4.x, b4.y, b4.z, b4.w};
#pragma unroll
            for (int i = 0; i < 4; i++)
#pragma unroll
                for (int j = 0; j < 4; j++) c[i][j] += av_[i] * bv_[j];
        }
        __syncthreads();
    }
#pragma unroll
    for (int i = 0; i < 4; i++) {
        int p = n0 + tx * 4 + i;
        int b = p >> 12, n = p & 4095;
#pragma unroll
        for (int j = 0; j < 4; j++) {
            int oc = oc0 + ty * 4 + j;
            if (oc < OC) {
                float v = c[i][j] + bias[oc];
                if (act) v = v * normcdff(v);
                size_t oidx = ((size_t)b * OC + oc) * NPIX + n;
                if (res) v += res[oidx];
                out[oidx] = v;
            }
        }
    }
}

// ---------------- flash attention: N=4096, d=32 per batch ----------------
__global__ __launch_bounds__(256) void flash_kernel() {
    __shared__ float Qs[64][33];
    __shared__ float Kt[32][64];
    __shared__ float Vs[64][33];
    __shared__ float Ps[64][64];
    int b = blockIdx.y;
    int q0 = blockIdx.x * 64;
    int tid = threadIdx.x, tx = tid & 15, ty = tid >> 4;
    const float* qkv = g_qkv + (size_t)b * 96 * NPIX;
    const float QSCALE = 1.4426950408889634f * 0.17677669529663687f;  // log2(e)/sqrt(32)
    for (int i = tid; i < 2048; i += 256) {
        int row = i & 63, col = i >> 6;
        Qs[row][col] = qkv[(size_t)col * NPIX + q0 + row] * QSCALE;
    }
    float m[4], l[4], o[4][2];
#pragma unroll
    for (int i = 0; i < 4; i++) { m[i] = -INFINITY; l[i] = 0.f; o[i][0] = 0.f; o[i][1] = 0.f; }
    __syncthreads();
    for (int kt = 0; kt < 64; kt++) {
        int k0 = kt * 64;
        for (int i = tid; i < 2048; i += 256) {
            int col = i & 63, cc = i >> 6;
            Kt[cc][col] = qkv[(size_t)(32 + cc) * NPIX + k0 + col];
            Vs[col][cc] = qkv[(size_t)(64 + cc) * NPIX + k0 + col];
        }
        __syncthreads();
        float s[4][4];
#pragma unroll
        for (int i = 0; i < 4; i++)
#pragma unroll
            for (int j = 0; j < 4; j++) s[i][j] = 0.f;
        for (int kc = 0; kc < 32; kc++) {
            float4 k4 = *(float4*)&Kt[kc][tx * 4];
            float kv[4] = {k4.x, k4.y, k4.z, k4.w};
#pragma unroll
            for (int i = 0; i < 4; i++) {
                float qv = Qs[ty * 4 + i][kc];
#pragma unroll
                for (int j = 0; j < 4; j++) s[i][j] += qv * kv[j];
            }
        }
#pragma unroll
        for (int i = 0; i < 4; i++) {
            float pm = fmaxf(fmaxf(s[i][0], s[i][1]), fmaxf(s[i][2], s[i][3]));
#pragma unroll
            for (int off = 1; off < 16; off <<= 1)
                pm = fmaxf(pm, __shfl_xor_sync(0xffffffffu, pm, off, 16));
            float mn = fmaxf(m[i], pm);
            float alpha = exp2f(m[i] - mn);
            m[i] = mn;
            l[i] *= alpha; o[i][0] *= alpha; o[i][1] *= alpha;
            float ps = 0.f;
#pragma unroll
            for (int j = 0; j < 4; j++) { s[i][j] = exp2f(s[i][j] - mn); ps += s[i][j]; }
#pragma unroll
            for (int off = 1; off < 16; off <<= 1)
                ps += __shfl_xor_sync(0xffffffffu, ps, off, 16);
            l[i] += ps;
            *(float4*)&Ps[ty * 4 + i][tx * 4] = make_float4(s[i][0], s[i][1], s[i][2], s[i][3]);
        }
        __syncthreads();
        for (int mm = 0; mm < 64; mm++) {
            float v0 = Vs[mm][tx * 2], v1 = Vs[mm][tx * 2 + 1];
#pragma unroll
            for (int i = 0; i < 4; i++) {
                float p = Ps[ty * 4 + i][mm];
                o[i][0] += p * v0; o[i][1] += p * v1;
            }
        }
        __syncthreads();
    }
    float* av = g_av + (size_t)b * 32 * NPIX;
#pragma unroll
    for (int i = 0; i < 4; i++) {
        float inv = 1.f / l[i];
        int q = q0 + ty * 4 + i;
        av[(size_t)(tx * 2 + 0) * NPIX + q] = o[i][0] * inv;
        av[(size_t)(tx * 2 + 1) * NPIX + q] = o[i][1] * inv;
    }
}

// ---------------- layernorm over 64 channels per pixel ----------------
__global__ void ln_kernel(const float* __restrict__ ln_g, const float* __restrict__ ln_b) {
    int p = blockIdx.x * 256 + threadIdx.x;
    int b = p >> 12, n = p & 4095;
    const float* ep = g_e + (size_t)b * 64 * NPIX + n;
    float v[64], mu = 0.f;
#pragma unroll
    for (int c = 0; c < 64; c++) { v[c] = ep[(size_t)c * NPIX]; mu += v[c]; }
    mu *= (1.f / 64.f);
    float var = 0.f;
#pragma unroll
    for (int c = 0; c < 64; c++) { float d = v[c] - mu; var += d * d; }
    var *= (1.f / 64.f);
    float inv = rsqrtf(var + 1e-5f);
    float* hp = g_h + (size_t)b * 64 * NPIX + n;
#pragma unroll
    for (int c = 0; c < 64; c++) hp[(size_t)c * NPIX] = (v[c] - mu) * inv * ln_g[c] + ln_b[c];
}

// ---------------- depthwise 3x3 conv + bias + GELU ----------------
__global__ void dw_kernel(const float* __restrict__ dw_w, const float* __restrict__ dw_b) {
    int idx = blockIdx.x * 256 + threadIdx.x;          // 4*256*4096
    int n = idx & 4095, c = (idx >> 12) & 255;
    int y = n >> 6, x = n & 63;
    const float* hp = g_h1 + (size_t)(idx >> 12) * NPIX;
    const float* w = dw_w + c * 9;
    float a = 0.f;
#pragma unroll
    for (int ky = 0; ky < 3; ky++) {
        int yy = y + ky - 1;
        if (yy < 0 || yy >= 64) continue;
#pragma unroll
        for (int kx = 0; kx < 3; kx++) {
            int xx = x + kx - 1;
            if (xx < 0 || xx >= 64) continue;
            a += hp[yy * 64 + xx] * w[ky * 3 + kx];
        }
    }
    a += dw_b[c];
    g_h2[idx] = a * normcdff(a);
}

// ---------------- host launcher ----------------
extern "C" void kernel_launch(void* const* d_in, const int* in_sizes, int n_in,
                              void* d_out, int out_size) {
    (void)in_sizes; (void)n_in; (void)out_size;
    const float* x       = (const float*)d_in[0];
    const float* skip    = (const float*)d_in[1];
    const float* qkv_w   = (const float*)d_in[2];
    const float* qkv_b   = (const float*)d_in[3];
    const float* proj_w  = (const float*)d_in[4];
    const float* proj_b  = (const float*)d_in[5];
    const float* edge_w  = (const float*)d_in[6];
    const float* thick_w = (const float*)d_in[7];
    const float* thick_b = (const float*)d_in[8];
    const float* off_w   = (const float*)d_in[9];
    const float* off_b   = (const float*)d_in[10];
    const float* deform_w= (const float*)d_in[11];
    const float* deform_b= (const float*)d_in[12];
    const float* ln_g    = (const float*)d_in[13];
    const float* ln_b    = (const float*)d_in[14];
    const float* mlp1_w  = (const float*)d_in[15];
    const float* mlp1_b  = (const float*)d_in[16];
    const float* dw_w    = (const float*)d_in[17];
    const float* dw_b    = (const float*)d_in[18];
    const float* mlp2_w  = (const float*)d_in[19];
    const float* mlp2_b  = (const float*)d_in[20];
    const float* down_w  = (const float*)d_in[21];
    const float* down_b  = (const float*)d_in[22];
    const float* up_w    = (const float*)d_in[23];
    const float* up_b    = (const float*)d_in[24];
    float* out = (float*)d_out;

    float *p_qkv, *p_av, *p_x2, *p_d, *p_e, *p_h, *p_h1, *p_h2, *p_t;
    float *p_qkvWT, *p_projWT, *p_downWT, *p_mlp1WT, *p_mlp2WT, *p_upWT;
    cudaGetSymbolAddress((void**)&p_qkv,    g_qkv);
    cudaGetSymbolAddress((void**)&p_av,     g_av);
    cudaGetSymbolAddress((void**)&p_x2,     g_x2);
    cudaGetSymbolAddress((void**)&p_d,      g_d);
    cudaGetSymbolAddress((void**)&p_e,      g_e);
    cudaGetSymbolAddress((void**)&p_h,      g_h);
    cudaGetSymbolAddress((void**)&p_h1,     g_h1);
    cudaGetSymbolAddress((void**)&p_h2,     g_h2);
    cudaGetSymbolAddress((void**)&p_t,      g_t);
    cudaGetSymbolAddress((void**)&p_qkvWT,  g_qkvWT);
    cudaGetSymbolAddress((void**)&p_projWT, g_projWT);
    cudaGetSymbolAddress((void**)&p_downWT, g_downWT);
    cudaGetSymbolAddress((void**)&p_mlp1WT, g_mlp1WT);
    cudaGetSymbolAddress((void**)&p_mlp2WT, g_mlp2WT);
    cudaGetSymbolAddress((void**)&p_upWT,   g_upWT);

    prep_kernel<<<128, 256>>>(qkv_w, proj_w, down_w, mlp1_w, mlp2_w, up_w, deform_w);
    upsample_kernel<<<dim3(64, 4), 64>>>(skip, thick_w, thick_b);
    edge_kernel<<<4096, 256>>>(edge_w);
    off_kernel<<<128, 128>>>(off_w, off_b);
    deform_kernel<<<128, 128>>>(deform_b);

    // qkv = conv1x1(x) ; flash attention ; proj + residual x
    gemm1x1<<<dim3(256, 2), 256>>>(x, 256, nullptr, 256, p_qkvWT, qkv_b, 96, nullptr, p_qkv, 0);
    flash_kernel<<<dim3(64, 4), 256>>>();
    gemm1x1<<<dim3(256, 4), 256>>>(p_av, 32, nullptr, 32, p_projWT, proj_b, 256, x, p_x2, 0);

    // down(concat[x2, d]) -> LN -> mlp1+gelu -> dw+gelu -> mlp2 + e -> up
    gemm1x1<<<dim3(256, 1), 256>>>(p_x2, 256, p_d, 320, p_downWT, down_b, 64, nullptr, p_e, 0);
    ln_kernel<<<64, 256>>>(ln_g, ln_b);
    gemm1x1<<<dim3(256, 4), 256>>>(p_h, 64, nullptr, 64, p_mlp1WT, mlp1_b, 256, nullptr, p_h1, 1);
    dw_kernel<<<16384, 256>>>(dw_w, dw_b);
    gemm1x1<<<dim3(256, 1), 256>>>(p_h2, 256, nullptr, 256, p_mlp2WT, mlp2_b, 64, p_e, p_t, 0);
    gemm1x1<<<dim3(256, 4), 256>>>(p_t, 64, nullptr, 64, p_upWT, up_b, 256, nullptr, out, 0);
}

// round 9
// speedup vs baseline: 1.1912x; 1.1912x over previous
#include <cuda_runtime.h>
#include <math.h>

#define NPIX 4096

// ---------------- f32x2 packed helpers (sm_100+) ----------------
__device__ __forceinline__ unsigned long long pack2(float lo, float hi) {
    unsigned long long r;
    asm("mov.b64 %0, {%1, %2};" : "=l"(r) : "f"(lo), "f"(hi));
    return r;
}
__device__ __forceinline__ float2 unpack2(unsigned long long v) {
    float2 r;
    asm("mov.b64 {%0, %1}, %2;" : "=f"(r.x), "=f"(r.y) : "l"(v));
    return r;
}
__device__ __forceinline__ void fma2(unsigned long long& d, unsigned long long a, unsigned long long b) {
    asm("fma.rn.f32x2 %0, %1, %2, %3;" : "=l"(d) : "l"(a), "l"(b), "l"(d));
}
__device__ __forceinline__ void mul2(unsigned long long& d, unsigned long long a, unsigned long long b) {
    asm("mul.rn.f32x2 %0, %1, %2;" : "=l"(d) : "l"(a), "l"(b));
}

// ---------------- scratch (device globals; allocation forbidden) ----------------
__device__ __align__(128) float g_skip_u[4 * NPIX * 64];   // NHWC [b][n][c]
__device__ __align__(128) float g_mean  [4 * NPIX];
__device__ __align__(128) float g_thick [4 * NPIX];
__device__ __align__(128) float g_edge  [4 * NPIX * 64];   // NHWC [b][n][c]
__device__ __align__(128) float g_off   [4 * NPIX * 18];   // NHWC [b][n][18]
__device__ __align__(128) float g_d     [4 * 64 * NPIX];   // NCHW
__device__ __align__(128) float g_qkv   [4 * 96 * NPIX];
__device__ __align__(128) float g_av    [4 * 32 * NPIX];
__device__ __align__(128) float g_x2    [4 * 256 * NPIX];
__device__ __align__(128) float g_e     [4 * 64 * NPIX];
__device__ __align__(128) float g_h     [4 * 64 * NPIX];
__device__ __align__(128) float g_h1    [4 * 256 * NPIX];
__device__ __align__(128) float g_h2    [4 * 256 * NPIX];
__device__ __align__(128) float g_t     [4 * 64 * NPIX];
// transposed weights [IC][OC]
__device__ __align__(128) float g_qkvWT [256 * 96];
__device__ __align__(128) float g_projWT[32 * 256];
__device__ __align__(128) float g_downWT[320 * 64];
__device__ __align__(128) float g_mlp1WT[64 * 256];
__device__ __align__(128) float g_mlp2WT[256 * 64];
__device__ __align__(128) float g_upWT  [64 * 256];
__device__ __align__(128) float g_dwT   [9 * 64 * 64];   // deform_w as [k][c][o]

// ---------------- prep: transpose weights ----------------
__global__ void prep_kernel(const float* __restrict__ qkv_w, const float* __restrict__ proj_w,
                            const float* __restrict__ down_w, const float* __restrict__ mlp1_w,
                            const float* __restrict__ mlp2_w, const float* __restrict__ up_w,
                            const float* __restrict__ deform_w) {
    int t0 = blockIdx.x * blockDim.x + threadIdx.x;
    int stride = gridDim.x * blockDim.x;
    for (int i = t0; i < 256 * 96; i += stride) { int ic = i / 96,  oc = i % 96;  g_qkvWT[i]  = qkv_w[oc * 256 + ic]; }
    for (int i = t0; i < 32 * 256; i += stride) { int ic = i / 256, oc = i % 256; g_projWT[i] = proj_w[oc * 32 + ic]; }
    for (int i = t0; i < 320 * 64; i += stride) { int ic = i / 64,  oc = i % 64;  g_downWT[i] = down_w[oc * 320 + ic]; }
    for (int i = t0; i < 64 * 256; i += stride) { int ic = i / 256, oc = i % 256; g_mlp1WT[i] = mlp1_w[oc * 64 + ic]; }
    for (int i = t0; i < 256 * 64; i += stride) { int ic = i / 64,  oc = i % 64;  g_mlp2WT[i] = mlp2_w[oc * 256 + ic]; }  // FIXED
    for (int i = t0; i < 64 * 256; i += stride) { int ic = i / 256, oc = i % 256; g_upWT[i]   = up_w[oc * 64 + ic]; }
    for (int i = t0; i < 9 * 64 * 64; i += stride) {
        int k = i >> 12, c = (i >> 6) & 63, o = i & 63;
        g_dwT[i] = deform_w[(o * 64 + c) * 9 + k];
    }
}

// ---------------- bilinear upsample (half-pixel) + channel mean + thick (NHWC out) ----------------
__global__ void upsample_kernel(const float* __restrict__ skip, const float* __restrict__ thick_w,
                                const float* __restrict__ thick_b) {
    int b = blockIdx.y, y = blockIdx.x, x = threadIdx.x;
    float sy = fminf(fmaxf(0.5f * y - 0.25f, 0.f), 31.f);
    float sx = fminf(fmaxf(0.5f * x - 0.25f, 0.f), 31.f);
    int y0 = (int)sy, x0 = (int)sx;
    int y1 = min(y0 + 1, 31), x1 = min(x0 + 1, 31);
    float wy = sy - (float)y0, wx = sx - (float)x0;
    float w00 = (1.f - wy) * (1.f - wx), w01 = (1.f - wy) * wx;
    float w10 = wy * (1.f - wx),         w11 = wy * wx;
    const float* sp = skip + (size_t)b * 64 * 1024;
    int pix = b * NPIX + y * 64 + x;
    float* up = g_skip_u + (size_t)pix * 64;
    float sum = 0.f, tsum = 0.f;
    for (int c = 0; c < 64; c++) {
        const float* p = sp + c * 1024;
        float v = w00 * p[y0 * 32 + x0] + w01 * p[y0 * 32 + x1]
                + w10 * p[y1 * 32 + x0] + w11 * p[y1 * 32 + x1];
        up[c] = v;
        sum += v;
        tsum += v * thick_w[c];
    }
    g_mean[pix] = sum * (1.f / 64.f);
    g_thick[pix] = 1.f / (1.f + expf(-(tsum + thick_b[0])));
}

// ---------------- edge conv: 3x3, 1 -> 64 ch, zero pad, no bias (NHWC out) ----------------
__global__ void edge_kernel(const float* __restrict__ edge_w) {
    int idx = blockIdx.x * 256 + threadIdx.x;          // 4*4096*64, oc fastest
    int oc = idx & 63, n = (idx >> 6) & 4095, b = idx >> 18;
    int y = n >> 6, x = n & 63;
    const float* mp = g_mean + b * NPIX;
    float a = 0.f;
#pragma unroll
    for (int ky = 0; ky < 3; ky++) {
        int yy = y + ky - 1;
        if (yy < 0 || yy >= 64) continue;
#pragma unroll
        for (int kx = 0; kx < 3; kx++) {
            int xx = x + kx - 1;
            if (xx < 0 || xx >= 64) continue;
            a += mp[yy * 64 + xx] * edge_w[oc * 9 + ky * 3 + kx];
        }
    }
    g_edge[idx] = a;
}

// ---------------- offset conv: 3x3, 64 -> 18, * (1 + 16*thick) ----------------
__global__ __launch_bounds__(512) void off_kernel(const float* __restrict__ off_w,
                                                  const float* __restrict__ off_b) {
    __shared__ float pool[64 * 9 * 18];                // ws, then reused as red[4*128*18]
    float* ws = pool;
    for (int i = threadIdx.x; i < 64 * 9 * 18; i += 512) {
        int o = i % 18, ck = i / 18;
        ws[i] = off_w[o * 576 + ck];                   // [c][k][o]
    }
    __syncthreads();
    int pl = threadIdx.x & 127, g = threadIdx.x >> 7;
    int pix = blockIdx.x * 128 + pl;
    int b = pix >> 12, n = pix & 4095;
    int y = n >> 6, x = n & 63;
    unsigned long long acc[9];
#pragma unroll
    for (int o = 0; o < 9; o++) acc[o] = 0ull;
    const float* ep = g_edge + (size_t)b * NPIX * 64;
#pragma unroll
    for (int ky = 0; ky < 3; ky++) {
        int yy = y + ky - 1;
        if (yy < 0 || yy >= 64) continue;
#pragma unroll
        for (int kx = 0; kx < 3; kx++) {
            int xx = x + kx - 1;
            if (xx < 0 || xx >= 64) continue;
            int k = ky * 3 + kx;
            const float4* col = (const float4*)(ep + (size_t)(yy * 64 + xx) * 64 + g * 16);
#pragma unroll
            for (int c4 = 0; c4 < 4; c4++) {
                float4 v4 = col[c4];
#pragma unroll
                for (int cc = 0; cc < 4; cc++) {
                    float v = (cc == 0) ? v4.x : (cc == 1) ? v4.y : (cc == 2) ? v4.z : v4.w;
                    unsigned long long vd = pack2(v, v);
                    const unsigned long long* wr =
                        (const unsigned long long*)&ws[((g * 16 + c4 * 4 + cc) * 9 + k) * 18];
#pragma unroll
                    for (int o = 0; o < 9; o++) fma2(acc[o], vd, wr[o]);
                }
            }
        }
    }
    __syncthreads();                                   // done with ws reads
    float* red = pool;                                 // [4][128][18]
#pragma unroll
    for (int o = 0; o < 9; o++)
        *(float2*)&red[((g * 128 + pl) * 18) + 2 * o] = unpack2(acc[o]);
    __syncthreads();
    for (int i = threadIdx.x; i < 128 * 18; i += 512) {
        int p2 = i / 18, o = i % 18;
        float s = red[(0 * 128 + p2) * 18 + o] + red[(1 * 128 + p2) * 18 + o]
                + red[(2 * 128 + p2) * 18 + o] + red[(3 * 128 + p2) * 18 + o];
        int gp = blockIdx.x * 128 + p2;
        float tscale = 1.f + 16.f * g_thick[gp];
        g_off[(size_t)gp * 18 + o] = (s + off_b[o]) * tscale;
    }
}

// ---------------- deformable conv 3x3 (DCNv1) + bias + edge ----------------
__global__ __launch_bounds__(64) void deform_kernel(const float* __restrict__ deform_b) {
    __shared__ float ws[4096];                         // [c][o] for current tap
    int pix = blockIdx.x * 64 + threadIdx.x;           // 16384
    int b = pix >> 12, n = pix & 4095;
    int y = n >> 6, x = n & 63;
    unsigned long long acc[32];
#pragma unroll
    for (int o = 0; o < 32; o++) acc[o] = 0ull;
    const float* su = g_skip_u + (size_t)b * NPIX * 64;
    const float* offp = g_off + (size_t)pix * 18;
    for (int k = 0; k < 9; k++) {
        __syncthreads();
        for (int i = threadIdx.x * 4; i < 4096; i += 64 * 4)
            *(float4*)&ws[i] = *(const float4*)&g_dwT[k * 4096 + i];
        __syncthreads();
        float py = (float)(y + k / 3 - 1) + offp[2 * k];
        float px = (float)(x + k % 3 - 1) + offp[2 * k + 1];
        float y0f = floorf(py), x0f = floorf(px);
        float wy = py - y0f, wx = px - x0f;
        int y0 = (int)y0f, x0 = (int)x0f;
        int y1 = y0 + 1, x1 = x0 + 1;
        bool vy0 = (y0 >= 0 && y0 < 64), vy1 = (y1 >= 0 && y1 < 64);
        bool vx0 = (x0 >= 0 && x0 < 64), vx1 = (x1 >= 0 && x1 < 64);
        float w00 = (vy0 && vx0) ? (1.f - wy) * (1.f - wx) : 0.f;
        float w01 = (vy0 && vx1) ? (1.f - wy) * wx : 0.f;
        float w10 = (vy1 && vx0) ? wy * (1.f - wx) : 0.f;
        float w11 = (vy1 && vx1) ? wy * wx : 0.f;
        int yc0 = min(max(y0, 0), 63), yc1 = min(max(y1, 0), 63);
        int xc0 = min(max(x0, 0), 63), xc1 = min(max(x1, 0), 63);
        const float4* p00 = (const float4*)(su + (size_t)(yc0 * 64 + xc0) * 64);
        const float4* p01 = (const float4*)(su + (size_t)(yc0 * 64 + xc1) * 64);
        const float4* p10 = (const float4*)(su + (size_t)(yc1 * 64 + xc0) * 64);
        const float4* p11 = (const float4*)(su + (size_t)(yc1 * 64 + xc1) * 64);
        for (int c4 = 0; c4 < 16; c4++) {
            float4 a0 = p00[c4], a1 = p01[c4], a2 = p10[c4], a3 = p11[c4];
            float4 val4;
            val4.x = w00 * a0.x + w01 * a1.x + w10 * a2.x + w11 * a3.x;
            val4.y = w00 * a0.y + w01 * a1.y + w10 * a2.y + w11 * a3.y;
            val4.z = w00 * a0.z + w01 * a1.z + w10 * a2.z + w11 * a3.z;
            val4.w = w00 * a0.w + w01 * a1.w + w10 * a2.w + w11 * a3.w;
#pragma unroll
            for (int cc = 0; cc < 4; cc++) {
                float v = (cc == 0) ? val4.x : (cc == 1) ? val4.y : (cc == 2) ? val4.z : val4.w;
                unsigned long long vd = pack2(v, v);
                const unsigned long long* wr = (const unsigned long long*)&ws[(c4 * 4 + cc) * 64];
#pragma unroll
                for (int o = 0; o < 32; o++) fma2(acc[o], vd, wr[o]);
            }
        }
    }
    const float* ep = g_edge + (size_t)pix * 64;
    float* dp = g_d + (size_t)b * 64 * NPIX + n;
#pragma unroll
    for (int o2 = 0; o2 < 32; o2++) {
        float2 a2 = unpack2(acc[o2]);
        dp[(size_t)(2 * o2 + 0) * NPIX] = a2.x + deform_b[2 * o2 + 0] + ep[2 * o2 + 0];
        dp[(size_t)(2 * o2 + 1) * NPIX] = a2.y + deform_b[2 * o2 + 1] + ep[2 * o2 + 1];
    }
}

// ---------------- generic 1x1-conv GEMM (f32x2 inner) ----------------
__global__ __launch_bounds__(256) void gemm1x1(const float* __restrict__ inA, int icA,
                                               const float* __restrict__ inB, int IC,
                                               const float* __restrict__ WT,
                                               const float* __restrict__ bias, int OC,
                                               const float* __restrict__ res,
                                               float* __restrict__ out, int act) {
    __shared__ float As[16][64];
    __shared__ float Bs[16][64];
    int tid = threadIdx.x;
    int tx = tid & 15, ty = tid >> 4;
    int n0 = blockIdx.x * 64;
    int oc0 = blockIdx.y * 64;
    unsigned long long cp[2][4];
#pragma unroll
    for (int i = 0; i < 2; i++)
#pragma unroll
        for (int j = 0; j < 4; j++) cp[i][j] = 0ull;
    int fidx = tid * 4;
    int lkk = fidx >> 6, lcol = fidx & 63;
    int gj = n0 + lcol;
    int lb = gj >> 12, ln = gj & 4095;
    int icB = IC - icA;
    for (int k0 = 0; k0 < IC; k0 += 16) {
        int ic = k0 + lkk;
        const float* src;
        if (ic < icA) src = inA + ((size_t)lb * icA + ic) * NPIX + ln;
        else          src = inB + ((size_t)lb * icB + (ic - icA)) * NPIX + ln;
        *(float4*)&As[lkk][lcol] = *(const float4*)src;
        float4 wv = make_float4(0.f, 0.f, 0.f, 0.f);
        if (oc0 + lcol < OC) wv = *(const float4*)&WT[(size_t)ic * OC + oc0 + lcol];
        *(float4*)&Bs[lkk][lcol] = wv;
        __syncthreads();
#pragma unroll
        for (int k = 0; k < 16; k++) {
            ulonglong2 a2 = *(ulonglong2*)&As[k][tx * 4];
            float4 b4 = *(float4*)&Bs[k][ty * 4];
            unsigned long long bd0 = pack2(b4.x, b4.x);
            unsigned long long bd1 = pack2(b4.y, b4.y);
            unsigned long long bd2 = pack2(b4.z, b4.z);
            unsigned long long bd3 = pack2(b4.w, b4.w);
            fma2(cp[0][0], a2.x, bd0); fma2(cp[1][0], a2.y, bd0);
            fma2(cp[0][1], a2.x, bd1); fma2(cp[1][1], a2.y, bd1);
            fma2(cp[0][2], a2.x, bd2); fma2(cp[1][2], a2.y, bd2);
            fma2(cp[0][3], a2.x, bd3); fma2(cp[1][3], a2.y, bd3);
        }
        __syncthreads();
    }
    float c[4][4];
#pragma unroll
    for (int ip = 0; ip < 2; ip++)
#pragma unroll
        for (int j = 0; j < 4; j++) {
            float2 u = unpack2(cp[ip][j]);
            c[ip * 2 + 0][j] = u.x;
            c[ip * 2 + 1][j] = u.y;
        }
#pragma unroll
    for (int i = 0; i < 4; i++) {
        int p = n0 + tx * 4 + i;
        int b = p >> 12, n = p & 4095;
#pragma unroll
        for (int j = 0; j < 4; j++) {
            int oc = oc0 + ty * 4 + j;
            if (oc < OC) {
                float v = c[i][j] + bias[oc];
                if (act) v = v * normcdff(v);
                size_t oidx = ((size_t)b * OC + oc) * NPIX + n;
                if (res) v += res[oidx];
                out[oidx] = v;
            }
        }
    }
}

// ---------------- flash attention: N=4096, d=32 per batch (f32x2 inner) ----------------
#define FLASH_SMEM_FLOATS (2048 + 2048 + 64 * 66 + 4096)
__global__ __launch_bounds__(256) void flash_kernel() {
    extern __shared__ float sm[];
    float* Qt = sm;                 // [32][64]  (channel-major)
    float* Kt = sm + 2048;          // [32][64]
    float* Vs = sm + 4096;          // [64][66]
    float* Ps = sm + 4096 + 64 * 66;// [64][64]
    int b = blockIdx.y;
    int q0 = blockIdx.x * 64;
    int tid = threadIdx.x, tx = tid & 15, ty = tid >> 4;
    const float* qkv = g_qkv + (size_t)b * 96 * NPIX;
    const float QSCALE = 1.4426950408889634f * 0.17677669529663687f;  // log2(e)/sqrt(32)
    for (int i = tid; i < 2048; i += 256) {
        int row = i & 63, col = i >> 6;
        Qt[col * 64 + row] = qkv[(size_t)col * NPIX + q0 + row] * QSCALE;
    }
    float m[4], l[4];
    unsigned long long o[4];
#pragma unroll
    for (int i = 0; i < 4; i++) { m[i] = -INFINITY; l[i] = 0.f; o[i] = 0ull; }
    __syncthreads();
    for (int kt = 0; kt < 64; kt++) {
        int k0 = kt * 64;
        for (int i = tid; i < 2048; i += 256) {
            int col = i & 63, cc = i >> 6;
            Kt[cc * 64 + col] = qkv[(size_t)(32 + cc) * NPIX + k0 + col];
            Vs[col * 66 + cc] = qkv[(size_t)(64 + cc) * NPIX + k0 + col];
        }
        __syncthreads();
        unsigned long long sp[2][4];
#pragma unroll
        for (int ip = 0; ip < 2; ip++)
#pragma unroll
            for (int j = 0; j < 4; j++) sp[ip][j] = 0ull;
#pragma unroll 4
        for (int kc = 0; kc < 32; kc++) {
            ulonglong2 q2 = *(ulonglong2*)&Qt[kc * 64 + ty * 4];
            float4 k4 = *(float4*)&Kt[kc * 64 + tx * 4];
            unsigned long long kd0 = pack2(k4.x, k4.x);
            unsigned long long kd1 = pack2(k4.y, k4.y);
            unsigned long long kd2 = pack2(k4.z, k4.z);
            unsigned long long kd3 = pack2(k4.w, k4.w);
            fma2(sp[0][0], q2.x, kd0); fma2(sp[1][0], q2.y, kd0);
            fma2(sp[0][1], q2.x, kd1); fma2(sp[1][1], q2.y, kd1);
            fma2(sp[0][2], q2.x, kd2); fma2(sp[1][2], q2.y, kd2);
            fma2(sp[0][3], q2.x, kd3); fma2(sp[1][3], q2.y, kd3);
        }
        float s[4][4];
#pragma unroll
        for (int ip = 0; ip < 2; ip++)
#pragma unroll
            for (int j = 0; j < 4; j++) {
                float2 u = unpack2(sp[ip][j]);
                s[ip * 2 + 0][j] = u.x;
                s[ip * 2 + 1][j] = u.y;
            }
#pragma unroll
        for (int i = 0; i < 4; i++) {
            float pm = fmaxf(fmaxf(s[i][0], s[i][1]), fmaxf(s[i][2], s[i][3]));
#pragma unroll
            for (int off = 1; off < 16; off <<= 1)
                pm = fmaxf(pm, __shfl_xor_sync(0xffffffffu, pm, off, 16));
            float mn = fmaxf(m[i], pm);
            float alpha = exp2f(m[i] - mn);
            m[i] = mn;
            l[i] *= alpha;
            unsigned long long ad = pack2(alpha, alpha);
            mul2(o[i], o[i], ad);
            float ps = 0.f;
#pragma unroll
            for (int j = 0; j < 4; j++) { s[i][j] = exp2f(s[i][j] - mn); ps += s[i][j]; }
#pragma unroll
            for (int off = 1; off < 16; off <<= 1)
                ps += __shfl_xor_sync(0xffffffffu, ps, off, 16);
            l[i] += ps;
            *(float4*)&Ps[(ty * 4 + i) * 64 + tx * 4] = make_float4(s[i][0], s[i][1], s[i][2], s[i][3]);
        }
        __syncthreads();
#pragma unroll 2
        for (int mm4 = 0; mm4 < 16; mm4++) {
            float4 p0 = *(float4*)&Ps[(ty * 4 + 0) * 64 + mm4 * 4];
            float4 p1 = *(float4*)&Ps[(ty * 4 + 1) * 64 + mm4 * 4];
            float4 p2 = *(float4*)&Ps[(ty * 4 + 2) * 64 + mm4 * 4];
            float4 p3 = *(float4*)&Ps[(ty * 4 + 3) * 64 + mm4 * 4];
#pragma unroll
            for (int t = 0; t < 4; t++) {
                unsigned long long vv = *(unsigned long long*)&Vs[(mm4 * 4 + t) * 66 + tx * 2];
                float f0 = (t == 0) ? p0.x : (t == 1) ? p0.y : (t == 2) ? p0.z : p0.w;
                float f1 = (t == 0) ? p1.x : (t == 1) ? p1.y : (t == 2) ? p1.z : p1.w;
                float f2 = (t == 0) ? p2.x : (t == 1) ? p2.y : (t == 2) ? p2.z : p2.w;
                float f3 = (t == 0) ? p3.x : (t == 1) ? p3.y : (t == 2) ? p3.z : p3.w;
                fma2(o[0], pack2(f0, f0), vv);
                fma2(o[1], pack2(f1, f1), vv);
                fma2(o[2], pack2(f2, f2), vv);
                fma2(o[3], pack2(f3, f3), vv);
            }
        }
        __syncthreads();
    }
    float* av = g_av + (size_t)b * 32 * NPIX;
#pragma unroll
    for (int i = 0; i < 4; i++) {
        float inv = 1.f / l[i];
        int q = q0 + ty * 4 + i;
        float2 ov = unpack2(o[i]);
        av[(size_t)(tx * 2 + 0) * NPIX + q] = ov.x * inv;
        av[(size_t)(tx * 2 + 1) * NPIX + q] = ov.y * inv;
    }
}

// ---------------- layernorm over 64 channels per pixel ----------------
__global__ void ln_kernel(const float* __restrict__ ln_g, const float* __restrict__ ln_b) {
    int p = blockIdx.x * 256 + threadIdx.x;
    int b = p >> 12, n = p & 4095;
    const float* ep = g_e + (size_t)b * 64 * NPIX + n;
    float v[64], mu = 0.f;
#pragma unroll
    for (int c = 0; c < 64; c++) { v[c] = ep[(size_t)c * NPIX]; mu += v[c]; }
    mu *= (1.f / 64.f);
    float var = 0.f;
#pragma unroll
    for (int c = 0; c < 64; c++) { float d = v[c] - mu; var += d * d; }
    var *= (1.f / 64.f);
    float inv = rsqrtf(var + 1e-5f);
    float* hp = g_h + (size_t)b * 64 * NPIX + n;
#pragma unroll
    for (int c = 0; c < 64; c++) hp[(size_t)c * NPIX] = (v[c] - mu) * inv * ln_g[c] + ln_b[c];
}

// ---------------- depthwise 3x3 conv + bias + GELU ----------------
__global__ void dw_kernel(const float* __restrict__ dw_w, const float* __restrict__ dw_b) {
    int idx = blockIdx.x * 256 + threadIdx.x;          // 4*256*4096
    int n = idx & 4095, c = (idx >> 12) & 255;
    int y = n >> 6, x = n & 63;
    const float* hp = g_h1 + (size_t)(idx >> 12) * NPIX;
    const float* w = dw_w + c * 9;
    float a = 0.f;
#pragma unroll
    for (int ky = 0; ky < 3; ky++) {
        int yy = y + ky - 1;
        if (yy < 0 || yy >= 64) continue;
#pragma unroll
        for (int kx = 0; kx < 3; kx++) {
            int xx = x + kx - 1;
            if (xx < 0 || xx >= 64) continue;
            a += hp[yy * 64 + xx] * w[ky * 3 + kx];
        }
    }
    a += dw_b[c];
    g_h2[idx] = a * normcdff(a);
}

// ---------------- host launcher ----------------
extern "C" void kernel_launch(void* const* d_in, const int* in_sizes, int n_in,
                              void* d_out, int out_size) {
    (void)in_sizes; (void)n_in; (void)out_size;
    const float* x       = (const float*)d_in[0];
    const float* skip    = (const float*)d_in[1];
    const float* qkv_w   = (const float*)d_in[2];
    const float* qkv_b   = (const float*)d_in[3];
    const float* proj_w  = (const float*)d_in[4];
    const float* proj_b  = (const float*)d_in[5];
    const float* edge_w  = (const float*)d_in[6];
    const float* thick_w = (const float*)d_in[7];
    const float* thick_b = (const float*)d_in[8];
    const float* off_w   = (const float*)d_in[9];
    const float* off_b   = (const float*)d_in[10];
    const float* deform_w= (const float*)d_in[11];
    const float* deform_b= (const float*)d_in[12];
    const float* ln_g    = (const float*)d_in[13];
    const float* ln_b    = (const float*)d_in[14];
    const float* mlp1_w  = (const float*)d_in[15];
    const float* mlp1_b  = (const float*)d_in[16];
    const float* dw_w    = (const float*)d_in[17];
    const float* dw_b    = (const float*)d_in[18];
    const float* mlp2_w  = (const float*)d_in[19];
    const float* mlp2_b  = (const float*)d_in[20];
    const float* down_w  = (const float*)d_in[21];
    const float* down_b  = (const float*)d_in[22];
    const float* up_w    = (const float*)d_in[23];
    const float* up_b    = (const float*)d_in[24];
    float* out = (float*)d_out;

    float *p_qkv, *p_av, *p_x2, *p_d, *p_e, *p_h, *p_h1, *p_h2, *p_t;
    float *p_qkvWT, *p_projWT, *p_downWT, *p_mlp1WT, *p_mlp2WT, *p_upWT;
    cudaGetSymbolAddress((void**)&p_qkv,    g_qkv);
    cudaGetSymbolAddress((void**)&p_av,     g_av);
    cudaGetSymbolAddress((void**)&p_x2,     g_x2);
    cudaGetSymbolAddress((void**)&p_d,      g_d);
    cudaGetSymbolAddress((void**)&p_e,      g_e);
    cudaGetSymbolAddress((void**)&p_h,      g_h);
    cudaGetSymbolAddress((void**)&p_h1,     g_h1);
    cudaGetSymbolAddress((void**)&p_h2,     g_h2);
    cudaGetSymbolAddress((void**)&p_t,      g_t);
    cudaGetSymbolAddress((void**)&p_qkvWT,  g_qkvWT);
    cudaGetSymbolAddress((void**)&p_projWT, g_projWT);
    cudaGetSymbolAddress((void**)&p_downWT, g_downWT);
    cudaGetSymbolAddress((void**)&p_mlp1WT, g_mlp1WT);
    cudaGetSymbolAddress((void**)&p_mlp2WT, g_mlp2WT);
    cudaGetSymbolAddress((void**)&p_upWT,   g_upWT);

    const int flash_smem = FLASH_SMEM_FLOATS * 4;
    cudaFuncSetAttribute(flash_kernel, cudaFuncAttributeMaxDynamicSharedMemorySize, flash_smem);

    prep_kernel<<<128, 256>>>(qkv_w, proj_w, down_w, mlp1_w, mlp2_w, up_w, deform_w);
    upsample_kernel<<<dim3(64, 4), 64>>>(skip, thick_w, thick_b);
    edge_kernel<<<4096, 256>>>(edge_w);
    off_kernel<<<128, 512>>>(off_w, off_b);
    deform_kernel<<<256, 64>>>(deform_b);

    // qkv = conv1x1(x) ; flash attention ; proj + residual x
    gemm1x1<<<dim3(256, 2), 256>>>(x, 256, nullptr, 256, p_qkvWT, qkv_b, 96, nullptr, p_qkv, 0);
    flash_kernel<<<dim3(64, 4), 256, flash_smem>>>();
    gemm1x1<<<dim3(256, 4), 256>>>(p_av, 32, nullptr, 32, p_projWT, proj_b, 256, x, p_x2, 0);

    // down(concat[x2, d]) -> LN -> mlp1+gelu -> dw+gelu -> mlp2 + e -> up
    gemm1x1<<<dim3(256, 1), 256>>>(p_x2, 256, p_d, 320, p_downWT, down_b, 64, nullptr, p_e, 0);
    ln_kernel<<<64, 256>>>(ln_g, ln_b);
    gemm1x1<<<dim3(256, 4), 256>>>(p_h, 64, nullptr, 64, p_mlp1WT, mlp1_b, 256, nullptr, p_h1, 1);
    dw_kernel<<<16384, 256>>>(dw_w, dw_b);
    gemm1x1<<<dim3(256, 1), 256>>>(p_h2, 256, nullptr, 256, p_mlp2WT, mlp2_b, 64, p_e, p_t, 0);
    gemm1x1<<<dim3(256, 4), 256>>>(p_t, 64, nullptr, 64, p_upWT, up_b, 256, nullptr, out, 0);
}

// round 11
// speedup vs baseline: 1.4891x; 1.2501x over previous
#include <cuda_runtime.h>
#include <math.h>

#define NPIX 4096

// ---------------- f32x2 packed helpers (sm_100+) ----------------
__device__ __forceinline__ unsigned long long pack2(float lo, float hi) {
    unsigned long long r;
    asm("mov.b64 %0, {%1, %2};" : "=l"(r) : "f"(lo), "f"(hi));
    return r;
}
__device__ __forceinline__ float2 unpack2(unsigned long long v) {
    float2 r;
    asm("mov.b64 {%0, %1}, %2;" : "=f"(r.x), "=f"(r.y) : "l"(v));
    return r;
}
__device__ __forceinline__ void fma2(unsigned long long& d, unsigned long long a, unsigned long long b) {
    asm("fma.rn.f32x2 %0, %1, %2, %3;" : "=l"(d) : "l"(a), "l"(b), "l"(d));
}

// ---------------- tf32 mma helpers ----------------
__device__ __forceinline__ unsigned tf32_of(float f) {
    unsigned r;
    asm("cvt.rna.tf32.f32 %0, %1;" : "=r"(r) : "f"(f));
    return r;
}
__device__ __forceinline__ void mma_tf32(float* d, const unsigned* a, unsigned b0, unsigned b1) {
    asm volatile(
        "mma.sync.aligned.m16n8k8.row.col.f32.tf32.tf32.f32 "
        "{%0,%1,%2,%3}, {%4,%5,%6,%7}, {%8,%9}, {%0,%1,%2,%3};"
        : "+f"(d[0]), "+f"(d[1]), "+f"(d[2]), "+f"(d[3])
        : "r"(a[0]), "r"(a[1]), "r"(a[2]), "r"(a[3]), "r"(b0), "r"(b1));
}

// ---------------- scratch (device globals; allocation forbidden) ----------------
__device__ __align__(128) float g_skip_u[4 * NPIX * 64];   // NHWC [b][n][c]
__device__ __align__(128) float g_mean  [4 * NPIX];
__device__ __align__(128) float g_thick [4 * NPIX];
__device__ __align__(128) float g_edge  [4 * NPIX * 64];   // NHWC [b][n][c]
__device__ __align__(128) float g_off   [4 * NPIX * 18];   // NHWC [b][n][18]
__device__ __align__(128) float g_d     [4 * 64 * NPIX];   // NCHW
__device__ __align__(128) float g_qkv   [4 * 96 * NPIX];
__device__ __align__(128) float g_av    [4 * 32 * NPIX];
__device__ __align__(128) float g_x2    [4 * 256 * NPIX];
__device__ __align__(128) float g_e     [4 * 64 * NPIX];
__device__ __align__(128) float g_h     [4 * 64 * NPIX];
__device__ __align__(128) float g_h1    [4 * 256 * NPIX];
__device__ __align__(128) float g_h2    [4 * 256 * NPIX];
__device__ __align__(128) float g_t     [4 * 64 * NPIX];
// transposed weights [IC][OC]
__device__ __align__(128) float g_qkvWT [256 * 96];
__device__ __align__(128) float g_projWT[32 * 256];
__device__ __align__(128) float g_downWT[320 * 64];
__device__ __align__(128) float g_mlp1WT[64 * 256];
__device__ __align__(128) float g_mlp2WT[256 * 64];
__device__ __align__(128) float g_upWT  [64 * 256];
__device__ __align__(128) float g_dwT   [9 * 64 * 64];   // deform_w as [k][c][o]

// ---------------- prep: transpose weights ----------------
__global__ void prep_kernel(const float* __restrict__ qkv_w, const float* __restrict__ proj_w,
                            const float* __restrict__ down_w, const float* __restrict__ mlp1_w,
                            const float* __restrict__ mlp2_w, const float* __restrict__ up_w,
                            const float* __restrict__ deform_w) {
    int t0 = blockIdx.x * blockDim.x + threadIdx.x;
    int stride = gridDim.x * blockDim.x;
    for (int i = t0; i < 256 * 96; i += stride) { int ic = i / 96,  oc = i % 96;  g_qkvWT[i]  = qkv_w[oc * 256 + ic]; }
    for (int i = t0; i < 32 * 256; i += stride) { int ic = i / 256, oc = i % 256; g_projWT[i] = proj_w[oc * 32 + ic]; }
    for (int i = t0; i < 320 * 64; i += stride) { int ic = i / 64,  oc = i % 64;  g_downWT[i] = down_w[oc * 320 + ic]; }
    for (int i = t0; i < 64 * 256; i += stride) { int ic = i / 256, oc = i % 256; g_mlp1WT[i] = mlp1_w[oc * 64 + ic]; }
    for (int i = t0; i < 256 * 64; i += stride) { int ic = i / 64,  oc = i % 64;  g_mlp2WT[i] = mlp2_w[oc * 256 + ic]; }
    for (int i = t0; i < 64 * 256; i += stride) { int ic = i / 256, oc = i % 256; g_upWT[i]   = up_w[oc * 64 + ic]; }
    for (int i = t0; i < 9 * 64 * 64; i += stride) {
        int k = i >> 12, c = (i >> 6) & 63, o = i & 63;
        g_dwT[i] = deform_w[(o * 64 + c) * 9 + k];
    }
}

// ---------------- bilinear upsample (half-pixel) + channel mean + thick (NHWC out) ----------------
__global__ void upsample_kernel(const float* __restrict__ skip, const float* __restrict__ thick_w,
                                const float* __restrict__ thick_b) {
    int b = blockIdx.y, y = blockIdx.x, x = threadIdx.x;
    float sy = fminf(fmaxf(0.5f * y - 0.25f, 0.f), 31.f);
    float sx = fminf(fmaxf(0.5f * x - 0.25f, 0.f), 31.f);
    int y0 = (int)sy, x0 = (int)sx;
    int y1 = min(y0 + 1, 31), x1 = min(x0 + 1, 31);
    float wy = sy - (float)y0, wx = sx - (float)x0;
    float w00 = (1.f - wy) * (1.f - wx), w01 = (1.f - wy) * wx;
    float w10 = wy * (1.f - wx),         w11 = wy * wx;
    const float* sp = skip + (size_t)b * 64 * 1024;
    int pix = b * NPIX + y * 64 + x;
    float* up = g_skip_u + (size_t)pix * 64;
    float sum = 0.f, tsum = 0.f;
    for (int c = 0; c < 64; c++) {
        const float* p = sp + c * 1024;
        float v = w00 * p[y0 * 32 + x0] + w01 * p[y0 * 32 + x1]
                + w10 * p[y1 * 32 + x0] + w11 * p[y1 * 32 + x1];
        up[c] = v;
        sum += v;
        tsum += v * thick_w[c];
    }
    g_mean[pix] = sum * (1.f / 64.f);
    g_thick[pix] = 1.f / (1.f + expf(-(tsum + thick_b[0])));
}

// ---------------- edge conv: 3x3, 1 -> 64 ch, zero pad, no bias (NHWC out) ----------------
__global__ void edge_kernel(const float* __restrict__ edge_w) {
    int idx = blockIdx.x * 256 + threadIdx.x;          // 4*4096*64, oc fastest
    int oc = idx & 63, n = (idx >> 6) & 4095, b = idx >> 18;
    int y = n >> 6, x = n & 63;
    const float* mp = g_mean + b * NPIX;
    float a = 0.f;
#pragma unroll
    for (int ky = 0; ky < 3; ky++) {
        int yy = y + ky - 1;
        if (yy < 0 || yy >= 64) continue;
#pragma unroll
        for (int kx = 0; kx < 3; kx++) {
            int xx = x + kx - 1;
            if (xx < 0 || xx >= 64) continue;
            a += mp[yy * 64 + xx] * edge_w[oc * 9 + ky * 3 + kx];
        }
    }
    g_edge[idx] = a;
}

// ---------------- offset conv: 3x3, 64 -> 18, * (1 + 16*thick) ----------------
__global__ __launch_bounds__(512) void off_kernel(const float* __restrict__ off_w,
                                                  const float* __restrict__ off_b) {
    __shared__ float pool[64 * 9 * 18];                // ws, then reused as red[4*128*18]
    float* ws = pool;
    for (int i = threadIdx.x; i < 64 * 9 * 18; i += 512) {
        int o = i % 18, ck = i / 18;
        ws[i] = off_w[o * 576 + ck];                   // [c][k][o]
    }
    __syncthreads();
    int pl = threadIdx.x & 127, g = threadIdx.x >> 7;
    int pix = blockIdx.x * 128 + pl;
    int b = pix >> 12, n = pix & 4095;
    int y = n >> 6, x = n & 63;
    unsigned long long acc[9];
#pragma unroll
    for (int o = 0; o < 9; o++) acc[o] = 0ull;
    const float* ep = g_edge + (size_t)b * NPIX * 64;
#pragma unroll
    for (int ky = 0; ky < 3; ky++) {
        int yy = y + ky - 1;
        if (yy < 0 || yy >= 64) continue;
#pragma unroll
        for (int kx = 0; kx < 3; kx++) {
            int xx = x + kx - 1;
            if (xx < 0 || xx >= 64) continue;
            int k = ky * 3 + kx;
            const float4* col = (const float4*)(ep + (size_t)(yy * 64 + xx) * 64 + g * 16);
#pragma unroll
            for (int c4 = 0; c4 < 4; c4++) {
                float4 v4 = col[c4];
#pragma unroll
                for (int cc = 0; cc < 4; cc++) {
                    float v = (cc == 0) ? v4.x : (cc == 1) ? v4.y : (cc == 2) ? v4.z : v4.w;
                    unsigned long long vd = pack2(v, v);
                    const unsigned long long* wr =
                        (const unsigned long long*)&ws[((g * 16 + c4 * 4 + cc) * 9 + k) * 18];
#pragma unroll
                    for (int o = 0; o < 9; o++) fma2(acc[o], vd, wr[o]);
                }
            }
        }
    }
    __syncthreads();                                   // done with ws reads
    float* red = pool;                                 // [4][128][18]
#pragma unroll
    for (int o = 0; o < 9; o++)
        *(float2*)&red[((g * 128 + pl) * 18) + 2 * o] = unpack2(acc[o]);
    __syncthreads();
    for (int i = threadIdx.x; i < 128 * 18; i += 512) {
        int p2 = i / 18, o = i % 18;
        float s = red[(0 * 128 + p2) * 18 + o] + red[(1 * 128 + p2) * 18 + o]
                + red[(2 * 128 + p2) * 18 + o] + red[(3 * 128 + p2) * 18 + o];
        int gp = blockIdx.x * 128 + p2;
        float tscale = 1.f + 16.f * g_thick[gp];
        g_off[(size_t)gp * 18 + o] = (s + off_b[o]) * tscale;
    }
}

// ---------------- deformable conv 3x3 (DCNv1) + bias + edge ----------------
__global__ __launch_bounds__(64) void deform_kernel(const float* __restrict__ deform_b) {
    __shared__ float ws[4096];                         // [c][o] for current tap
    int pix = blockIdx.x * 64 + threadIdx.x;           // 16384
    int b = pix >> 12, n = pix & 4095;
    int y = n >> 6, x = n & 63;
    unsigned long long acc[32];
#pragma unroll
    for (int o = 0; o < 32; o++) acc[o] = 0ull;
    const float* su = g_skip_u + (size_t)b * NPIX * 64;
    const float* offp = g_off + (size_t)pix * 18;
    for (int k = 0; k < 9; k++) {
        __syncthreads();
        for (int i = threadIdx.x * 4; i < 4096; i += 64 * 4)
            *(float4*)&ws[i] = *(const float4*)&g_dwT[k * 4096 + i];
        __syncthreads();
        float py = (float)(y + k / 3 - 1) + offp[2 * k];
        float px = (float)(x + k % 3 - 1) + offp[2 * k + 1];
        float y0f = floorf(py), x0f = floorf(px);
        float wy = py - y0f, wx = px - x0f;
        int y0 = (int)y0f, x0 = (int)x0f;
        int y1 = y0 + 1, x1 = x0 + 1;
        bool vy0 = (y0 >= 0 && y0 < 64), vy1 = (y1 >= 0 && y1 < 64);
        bool vx0 = (x0 >= 0 && x0 < 64), vx1 = (x1 >= 0 && x1 < 64);
        float w00 = (vy0 && vx0) ? (1.f - wy) * (1.f - wx) : 0.f;
        float w01 = (vy0 && vx1) ? (1.f - wy) * wx : 0.f;
        float w10 = (vy1 && vx0) ? wy * (1.f - wx) : 0.f;
        float w11 = (vy1 && vx1) ? wy * wx : 0.f;
        int yc0 = min(max(y0, 0), 63), yc1 = min(max(y1, 0), 63);
        int xc0 = min(max(x0, 0), 63), xc1 = min(max(x1, 0), 63);
        const float4* p00 = (const float4*)(su + (size_t)(yc0 * 64 + xc0) * 64);
        const float4* p01 = (const float4*)(su + (size_t)(yc0 * 64 + xc1) * 64);
        const float4* p10 = (const float4*)(su + (size_t)(yc1 * 64 + xc0) * 64);
        const float4* p11 = (const float4*)(su + (size_t)(yc1 * 64 + xc1) * 64);
        for (int c4 = 0; c4 < 16; c4++) {
            float4 a0 = p00[c4], a1 = p01[c4], a2 = p10[c4], a3 = p11[c4];
            float4 val4;
            val4.x = w00 * a0.x + w01 * a1.x + w10 * a2.x + w11 * a3.x;
            val4.y = w00 * a0.y + w01 * a1.y + w10 * a2.y + w11 * a3.y;
            val4.z = w00 * a0.z + w01 * a1.z + w10 * a2.z + w11 * a3.z;
            val4.w = w00 * a0.w + w01 * a1.w + w10 * a2.w + w11 * a3.w;
#pragma unroll
            for (int cc = 0; cc < 4; cc++) {
                float v = (cc == 0) ? val4.x : (cc == 1) ? val4.y : (cc == 2) ? val4.z : val4.w;
                unsigned long long vd = pack2(v, v);
                const unsigned long long* wr = (const unsigned long long*)&ws[(c4 * 4 + cc) * 64];
#pragma unroll
                for (int o = 0; o < 32; o++) fma2(acc[o], vd, wr[o]);
            }
        }
    }
    const float* ep = g_edge + (size_t)pix * 64;
    float* dp = g_d + (size_t)b * 64 * NPIX + n;
#pragma unroll
    for (int o2 = 0; o2 < 32; o2++) {
        float2 a2 = unpack2(acc[o2]);
        dp[(size_t)(2 * o2 + 0) * NPIX] = a2.x + deform_b[2 * o2 + 0] + ep[2 * o2 + 0];
        dp[(size_t)(2 * o2 + 1) * NPIX] = a2.y + deform_b[2 * o2 + 1] + ep[2 * o2 + 1];
    }
}

// ---------------- generic 1x1-conv GEMM (f32x2 inner) ----------------
__global__ __launch_bounds__(256) void gemm1x1(const float* __restrict__ inA, int icA,
                                               const float* __restrict__ inB, int IC,
                                               const float* __restrict__ WT,
                                               const float* __restrict__ bias, int OC,
                                               const float* __restrict__ res,
                                               float* __restrict__ out, int act) {
    __shared__ float As[16][64];
    __shared__ float Bs[16][64];
    int tid = threadIdx.x;
    int tx = tid & 15, ty = tid >> 4;
    int n0 = blockIdx.x * 64;
    int oc0 = blockIdx.y * 64;
    unsigned long long cp[2][4];
#pragma unroll
    for (int i = 0; i < 2; i++)
#pragma unroll
        for (int j = 0; j < 4; j++) cp[i][j] = 0ull;
    int fidx = tid * 4;
    int lkk = fidx >> 6, lcol = fidx & 63;
    int gj = n0 + lcol;
    int lb = gj >> 12, ln = gj & 4095;
    int icB = IC - icA;
    for (int k0 = 0; k0 < IC; k0 += 16) {
        int ic = k0 + lkk;
        const float* src;
        if (ic < icA) src = inA + ((size_t)lb * icA + ic) * NPIX + ln;
        else          src = inB + ((size_t)lb * icB + (ic - icA)) * NPIX + ln;
        *(float4*)&As[lkk][lcol] = *(const float4*)src;
        float4 wv = make_float4(0.f, 0.f, 0.f, 0.f);
        if (oc0 + lcol < OC) wv = *(const float4*)&WT[(size_t)ic * OC + oc0 + lcol];
        *(float4*)&Bs[lkk][lcol] = wv;
        __syncthreads();
#pragma unroll
        for (int k = 0; k < 16; k++) {
            ulonglong2 a2 = *(ulonglong2*)&As[k][tx * 4];
            float4 b4 = *(float4*)&Bs[k][ty * 4];
            unsigned long long bd0 = pack2(b4.x, b4.x);
            unsigned long long bd1 = pack2(b4.y, b4.y);
            unsigned long long bd2 = pack2(b4.z, b4.z);
            unsigned long long bd3 = pack2(b4.w, b4.w);
            fma2(cp[0][0], a2.x, bd0); fma2(cp[1][0], a2.y, bd0);
            fma2(cp[0][1], a2.x, bd1); fma2(cp[1][1], a2.y, bd1);
            fma2(cp[0][2], a2.x, bd2); fma2(cp[1][2], a2.y, bd2);
            fma2(cp[0][3], a2.x, bd3); fma2(cp[1][3], a2.y, bd3);
        }
        __syncthreads();
    }
    float c[4][4];
#pragma unroll
    for (int ip = 0; ip < 2; ip++)
#pragma unroll
        for (int j = 0; j < 4; j++) {
            float2 u = unpack2(cp[ip][j]);
            c[ip * 2 + 0][j] = u.x;
            c[ip * 2 + 1][j] = u.y;
        }
#pragma unroll
    for (int i = 0; i < 4; i++) {
        int p = n0 + tx * 4 + i;
        int b = p >> 12, n = p & 4095;
#pragma unroll
        for (int j = 0; j < 4; j++) {
            int oc = oc0 + ty * 4 + j;
            if (oc < OC) {
                float v = c[i][j] + bias[oc];
                if (act) v = v * normcdff(v);
                size_t oidx = ((size_t)b * OC + oc) * NPIX + n;
                if (res) v += res[oidx];
                out[oidx] = v;
            }
        }
    }
}

// ---------------- flash attention (tf32 mma.sync): N=4096, d=32 per batch ----------------
// Block: 128 threads = 4 warps, q-tile 64 (16 q-rows/warp). grid (64, 4).
__global__ __launch_bounds__(128) void flash_kernel() {
    __shared__ float Kt_s[32 * 72];        // [ch][key], stride 72 (conflict-free frags)
    __shared__ float Vs_s[64 * 41];        // [key][ch], stride 41
    __shared__ float Ps_s[4 * 16 * 72];    // per-warp P tile [q][key], stride 72
    int b = blockIdx.y;
    int q0 = blockIdx.x * 64;
    int tid = threadIdx.x;
    int w = tid >> 5, lane = tid & 31;
    int g = lane >> 2, t = lane & 3;       // groupID, threadID-in-group
    const float* qkv = g_qkv + (size_t)b * 96 * NPIX;
    const float QSCALE = 1.4426950408889634f * 0.17677669529663687f;  // log2(e)/sqrt(32)
    int qrow = q0 + w * 16 + g;            // rows qrow (c0,c1) and qrow+8 (c2,c3)

    // Preload Q fragments (A operand), tf32, scaled. qa[kchunk][0..3]
    unsigned qa[4][4];
#pragma unroll
    for (int kc = 0; kc < 4; kc++) {
        qa[kc][0] = tf32_of(qkv[(size_t)(kc * 8 + t) * NPIX + qrow] * QSCALE);
        qa[kc][1] = tf32_of(qkv[(size_t)(kc * 8 + t) * NPIX + qrow + 8] * QSCALE);
        qa[kc][2] = tf32_of(qkv[(size_t)(kc * 8 + t + 4) * NPIX + qrow] * QSCALE);
        qa[kc][3] = tf32_of(qkv[(size_t)(kc * 8 + t + 4) * NPIX + qrow + 8] * QSCALE);
    }

    float m0 = -INFINITY, m1 = -INFINITY, l0 = 0.f, l1 = 0.f;
    float o[4][4];                          // [ch-tile][c0..c3]
#pragma unroll
    for (int i = 0; i < 4; i++)
#pragma unroll
        for (int j = 0; j < 4; j++) o[i][j] = 0.f;
    float* Pw = Ps_s + w * 16 * 72;

    for (int kt = 0; kt < 64; kt++) {
        int k0 = kt * 64;
        __syncthreads();                    // prev-tile Vs/Kt reads done
        for (int i = tid; i < 2048; i += 128) {
            int ch = i >> 6, key = i & 63;
            Kt_s[ch * 72 + key] = __uint_as_float(tf32_of(qkv[(size_t)(32 + ch) * NPIX + k0 + key]));
            Vs_s[key * 41 + ch] = __uint_as_float(tf32_of(qkv[(size_t)(64 + ch) * NPIX + k0 + key]));
        }
        __syncthreads();

        // S = Q @ K^T : 8 n-tiles (keys) x 4 k-chunks (channels)
        float s[8][4];
#pragma unroll
        for (int nt = 0; nt < 8; nt++)
#pragma unroll
            for (int j = 0; j < 4; j++) s[nt][j] = 0.f;
#pragma unroll
        for (int nt = 0; nt < 8; nt++) {
#pragma unroll
            for (int kc = 0; kc < 4; kc++) {
                unsigned b0 = __float_as_uint(Kt_s[(kc * 8 + t) * 72 + nt * 8 + g]);
                unsigned b1 = __float_as_uint(Kt_s[(kc * 8 + t + 4) * 72 + nt * 8 + g]);
                mma_tf32(s[nt], qa[kc], b0, b1);
            }
        }

        // online softmax on C-fragment rows (row0 = qrow via c0,c1; row1 = qrow+8 via c2,c3)
        float pm0 = -INFINITY, pm1 = -INFINITY;
#pragma unroll
        for (int nt = 0; nt < 8; nt++) {
            pm0 = fmaxf(pm0, fmaxf(s[nt][0], s[nt][1]));
            pm1 = fmaxf(pm1, fmaxf(s[nt][2], s[nt][3]));
        }
        pm0 = fmaxf(pm0, __shfl_xor_sync(0xffffffffu, pm0, 1, 4));
        pm0 = fmaxf(pm0, __shfl_xor_sync(0xffffffffu, pm0, 2, 4));
        pm1 = fmaxf(pm1, __shfl_xor_sync(0xffffffffu, pm1, 1, 4));
        pm1 = fmaxf(pm1, __shfl_xor_sync(0xffffffffu, pm1, 2, 4));
        float mn0 = fmaxf(m0, pm0), mn1 = fmaxf(m1, pm1);
        float al0 = exp2f(m0 - mn0), al1 = exp2f(m1 - mn1);
        m0 = mn0; m1 = mn1;
        l0 *= al0; l1 *= al1;
#pragma unroll
        for (int c = 0; c < 4; c++) {
            o[c][0] *= al0; o[c][1] *= al0;
            o[c][2] *= al1; o[c][3] *= al1;
        }
        float ps0 = 0.f, ps1 = 0.f;
#pragma unroll
        for (int nt = 0; nt < 8; nt++) {
            float p0 = exp2f(s[nt][0] - mn0);
            float p1 = exp2f(s[nt][1] - mn0);
            float p2 = exp2f(s[nt][2] - mn1);
            float p3 = exp2f(s[nt][3] - mn1);
            ps0 += p0 + p1; ps1 += p2 + p3;
            // store P as tf32 into per-warp smem (C layout: cols 2t, 2t+1)
            uint2 lo = make_uint2(tf32_of(p0), tf32_of(p1));
            uint2 hi = make_uint2(tf32_of(p2), tf32_of(p3));
            *(uint2*)&Pw[g * 72 + nt * 8 + 2 * t] = lo;
            *(uint2*)&Pw[(g + 8) * 72 + nt * 8 + 2 * t] = hi;
        }
        ps0 += __shfl_xor_sync(0xffffffffu, ps0, 1, 4);
        ps0 += __shfl_xor_sync(0xffffffffu, ps0, 2, 4);
        ps1 += __shfl_xor_sync(0xffffffffu, ps1, 1, 4);
        ps1 += __shfl_xor_sync(0xffffffffu, ps1, 2, 4);
        l0 += ps0; l1 += ps1;
        __syncwarp();

        // O += P @ V : A = P (k = keys, 8 chunks), B = V (4 ch-tiles)
#pragma unroll
        for (int c = 0; c < 8; c++) {
            unsigned pa[4];
            pa[0] = __float_as_uint(Pw[g * 72 + c * 8 + t]);
            pa[1] = __float_as_uint(Pw[(g + 8) * 72 + c * 8 + t]);
            pa[2] = __float_as_uint(Pw[g * 72 + c * 8 + t + 4]);
            pa[3] = __float_as_uint(Pw[(g + 8) * 72 + c * 8 + t + 4]);
#pragma unroll
            for (int nt2 = 0; nt2 < 4; nt2++) {
                unsigned b0 = __float_as_uint(Vs_s[(c * 8 + t) * 41 + nt2 * 8 + g]);
                unsigned b1 = __float_as_uint(Vs_s[(c * 8 + t + 4) * 41 + nt2 * 8 + g]);
                mma_tf32(o[nt2], pa, b0, b1);
            }
        }
        __syncwarp();
    }

    float inv0 = 1.f / l0, inv1 = 1.f / l1;
    float* av = g_av + (size_t)b * 32 * NPIX;
#pragma unroll
    for (int nt2 = 0; nt2 < 4; nt2++) {
        int ch = nt2 * 8 + 2 * t;
        av[(size_t)ch * NPIX + qrow]           = o[nt2][0] * inv0;
        av[(size_t)(ch + 1) * NPIX + qrow]     = o[nt2][1] * inv0;
        av[(size_t)ch * NPIX + qrow + 8]       = o[nt2][2] * inv1;
        av[(size_t)(ch + 1) * NPIX + qrow + 8] = o[nt2][3] * inv1;
    }
}

// ---------------- layernorm over 64 channels per pixel ----------------
__global__ void ln_kernel(const float* __restrict__ ln_g, const float* __restrict__ ln_b) {
    int p = blockIdx.x * 256 + threadIdx.x;
    int b = p >> 12, n = p & 4095;
    const float* ep = g_e + (size_t)b * 64 * NPIX + n;
    float v[64], mu = 0.f;
#pragma unroll
    for (int c = 0; c < 64; c++) { v[c] = ep[(size_t)c * NPIX]; mu += v[c]; }
    mu *= (1.f / 64.f);
    float var = 0.f;
#pragma unroll
    for (int c = 0; c < 64; c++) { float d = v[c] - mu; var += d * d; }
    var *= (1.f / 64.f);
    float inv = rsqrtf(var + 1e-5f);
    float* hp = g_h + (size_t)b * 64 * NPIX + n;
#pragma unroll
    for (int c = 0; c < 64; c++) hp[(size_t)c * NPIX] = (v[c] - mu) * inv * ln_g[c] + ln_b[c];
}

// ---------------- depthwise 3x3 conv + bias + GELU ----------------
__global__ void dw_kernel(const float* __restrict__ dw_w, const float* __restrict__ dw_b) {
    int idx = blockIdx.x * 256 + threadIdx.x;          // 4*256*4096
    int n = idx & 4095, c = (idx >> 12) & 255;
    int y = n >> 6, x = n & 63;
    const float* hp = g_h1 + (size_t)(idx >> 12) * NPIX;
    const float* w = dw_w + c * 9;
    float a = 0.f;
#pragma unroll
    for (int ky = 0; ky < 3; ky++) {
        int yy = y + ky - 1;
        if (yy < 0 || yy >= 64) continue;
#pragma unroll
        for (int kx = 0; kx < 3; kx++) {
            int xx = x + kx - 1;
            if (xx < 0 || xx >= 64) continue;
            a += hp[yy * 64 + xx] * w[ky * 3 + kx];
        }
    }
    a += dw_b[c];
    g_h2[idx] = a * normcdff(a);
}

// ---------------- host launcher ----------------
extern "C" void kernel_launch(void* const* d_in, const int* in_sizes, int n_in,
                              void* d_out, int out_size) {
    (void)in_sizes; (void)n_in; (void)out_size;
    const float* x       = (const float*)d_in[0];
    const float* skip    = (const float*)d_in[1];
    const float* qkv_w   = (const float*)d_in[2];
    const float* qkv_b   = (const float*)d_in[3];
    const float* proj_w  = (const float*)d_in[4];
    const float* proj_b  = (const float*)d_in[5];
    const float* edge_w  = (const float*)d_in[6];
    const float* thick_w = (const float*)d_in[7];
    const float* thick_b = (const float*)d_in[8];
    const float* off_w   = (const float*)d_in[9];
    const float* off_b   = (const float*)d_in[10];
    const float* deform_w= (const float*)d_in[11];
    const float* deform_b= (const float*)d_in[12];
    const float* ln_g    = (const float*)d_in[13];
    const float* ln_b    = (const float*)d_in[14];
    const float* mlp1_w  = (const float*)d_in[15];
    const float* mlp1_b  = (const float*)d_in[16];
    const float* dw_w    = (const float*)d_in[17];
    const float* dw_b    = (const float*)d_in[18];
    const float* mlp2_w  = (const float*)d_in[19];
    const float* mlp2_b  = (const float*)d_in[20];
    const float* down_w  = (const float*)d_in[21];
    const float* down_b  = (const float*)d_in[22];
    const float* up_w    = (const float*)d_in[23];
    const float* up_b    = (const float*)d_in[24];
    float* out = (float*)d_out;

    float *p_qkv, *p_av, *p_x2, *p_d, *p_e, *p_h, *p_h1, *p_h2, *p_t;
    float *p_qkvWT, *p_projWT, *p_downWT, *p_mlp1WT, *p_mlp2WT, *p_upWT;
    cudaGetSymbolAddress((void**)&p_qkv,    g_qkv);
    cudaGetSymbolAddress((void**)&p_av,     g_av);
    cudaGetSymbolAddress((void**)&p_x2,     g_x2);
    cudaGetSymbolAddress((void**)&p_d,      g_d);
    cudaGetSymbolAddress((void**)&p_e,      g_e);
    cudaGetSymbolAddress((void**)&p_h,      g_h);
    cudaGetSymbolAddress((void**)&p_h1,     g_h1);
    cudaGetSymbolAddress((void**)&p_h2,     g_h2);
    cudaGetSymbolAddress((void**)&p_t,      g_t);
    cudaGetSymbolAddress((void**)&p_qkvWT,  g_qkvWT);
    cudaGetSymbolAddress((void**)&p_projWT, g_projWT);
    cudaGetSymbolAddress((void**)&p_downWT, g_downWT);
    cudaGetSymbolAddress((void**)&p_mlp1WT, g_mlp1WT);
    cudaGetSymbolAddress((void**)&p_mlp2WT, g_mlp2WT);
    cudaGetSymbolAddress((void**)&p_upWT,   g_upWT);

    prep_kernel<<<128, 256>>>(qkv_w, proj_w, down_w, mlp1_w, mlp2_w, up_w, deform_w);
    upsample_kernel<<<dim3(64, 4), 64>>>(skip, thick_w, thick_b);
    edge_kernel<<<4096, 256>>>(edge_w);
    off_kernel<<<128, 512>>>(off_w, off_b);
    deform_kernel<<<256, 64>>>(deform_b);

    // qkv = conv1x1(x) ; flash attention (tf32 tensor cores) ; proj + residual x
    gemm1x1<<<dim3(256, 2), 256>>>(x, 256, nullptr, 256, p_qkvWT, qkv_b, 96, nullptr, p_qkv, 0);
    flash_kernel<<<dim3(64, 4), 128>>>();
    gemm1x1<<<dim3(256, 4), 256>>>(p_av, 32, nullptr, 32, p_projWT, proj_b, 256, x, p_x2, 0);

    // down(concat[x2, d]) -> LN -> mlp1+gelu -> dw+gelu -> mlp2 + e -> up
    gemm1x1<<<dim3(256, 1), 256>>>(p_x2, 256, p_d, 320, p_downWT, down_b, 64, nullptr, p_e, 0);
    ln_kernel<<<64, 256>>>(ln_g, ln_b);
    gemm1x1<<<dim3(256, 4), 256>>>(p_h, 64, nullptr, 64, p_mlp1WT, mlp1_b, 256, nullptr, p_h1, 1);
    dw_kernel<<<16384, 256>>>(dw_w, dw_b);
    gemm1x1<<<dim3(256, 1), 256>>>(p_h2, 256, nullptr, 256, p_mlp2WT, mlp2_b, 64, p_e, p_t, 0);
    gemm1x1<<<dim3(256, 4), 256>>>(p_t, 64, nullptr, 64, p_upWT, up_b, 256, nullptr, out, 0);
}

// round 12
// speedup vs baseline: 1.6639x; 1.1174x over previous
#include <cuda_runtime.h>
#include <math.h>

#define NPIX 4096

// ---------------- f32x2 packed helpers (sm_100+) ----------------
__device__ __forceinline__ unsigned long long pack2(float lo, float hi) {
    unsigned long long r;
    asm("mov.b64 %0, {%1, %2};" : "=l"(r) : "f"(lo), "f"(hi));
    return r;
}
__device__ __forceinline__ float2 unpack2(unsigned long long v) {
    float2 r;
    asm("mov.b64 {%0, %1}, %2;" : "=f"(r.x), "=f"(r.y) : "l"(v));
    return r;
}
__device__ __forceinline__ void fma2(unsigned long long& d, unsigned long long a, unsigned long long b) {
    asm("fma.rn.f32x2 %0, %1, %2, %3;" : "=l"(d) : "l"(a), "l"(b), "l"(d));
}

// ---------------- tf32 mma helpers ----------------
__device__ __forceinline__ unsigned tf32_of(float f) {
    unsigned r;
    asm("cvt.rna.tf32.f32 %0, %1;" : "=r"(r) : "f"(f));
    return r;
}
__device__ __forceinline__ void mma_tf32(float* d, const unsigned* a, unsigned b0, unsigned b1) {
    asm volatile(
        "mma.sync.aligned.m16n8k8.row.col.f32.tf32.tf32.f32 "
        "{%0,%1,%2,%3}, {%4,%5,%6,%7}, {%8,%9}, {%0,%1,%2,%3};"
        : "+f"(d[0]), "+f"(d[1]), "+f"(d[2]), "+f"(d[3])
        : "r"(a[0]), "r"(a[1]), "r"(a[2]), "r"(a[3]), "r"(b0), "r"(b1));
}

// ---------------- scratch (device globals; allocation forbidden) ----------------
__device__ __align__(128) float g_skip_u[4 * NPIX * 64];   // NHWC [b][n][c]
__device__ __align__(128) float g_mean  [4 * NPIX];
__device__ __align__(128) float g_thick [4 * NPIX];
__device__ __align__(128) float g_edge  [4 * NPIX * 64];   // NHWC [b][n][c]
__device__ __align__(128) float g_off   [4 * NPIX * 18];   // NHWC [b][n][18]
__device__ __align__(128) float g_d     [4 * 64 * NPIX];   // NCHW
__device__ __align__(128) float g_qkv   [4 * 96 * NPIX];
__device__ __align__(128) float g_av    [4 * 32 * NPIX];
__device__ __align__(128) float g_x2    [4 * 256 * NPIX];
__device__ __align__(128) float g_e     [4 * 64 * NPIX];
__device__ __align__(128) float g_h     [4 * 64 * NPIX];
__device__ __align__(128) float g_h1    [4 * 256 * NPIX];
__device__ __align__(128) float g_h2    [4 * 256 * NPIX];
__device__ __align__(128) float g_t     [4 * 64 * NPIX];
// transposed weights [IC][OC]
__device__ __align__(128) float g_qkvWT [256 * 96];
__device__ __align__(128) float g_projWT[32 * 256];
__device__ __align__(128) float g_downWT[320 * 64];
__device__ __align__(128) float g_mlp1WT[64 * 256];
__device__ __align__(128) float g_mlp2WT[256 * 64];
__device__ __align__(128) float g_upWT  [64 * 256];
__device__ __align__(128) float g_dwT   [9 * 64 * 64];   // deform_w as [k][c][o]

// ---------------- prep: transpose weights ----------------
__global__ void prep_kernel(const float* __restrict__ qkv_w, const float* __restrict__ proj_w,
                            const float* __restrict__ down_w, const float* __restrict__ mlp1_w,
                            const float* __restrict__ mlp2_w, const float* __restrict__ up_w,
                            const float* __restrict__ deform_w) {
    int t0 = blockIdx.x * blockDim.x + threadIdx.x;
    int stride = gridDim.x * blockDim.x;
    for (int i = t0; i < 256 * 96; i += stride) { int ic = i / 96,  oc = i % 96;  g_qkvWT[i]  = qkv_w[oc * 256 + ic]; }
    for (int i = t0; i < 32 * 256; i += stride) { int ic = i / 256, oc = i % 256; g_projWT[i] = proj_w[oc * 32 + ic]; }
    for (int i = t0; i < 320 * 64; i += stride) { int ic = i / 64,  oc = i % 64;  g_downWT[i] = down_w[oc * 320 + ic]; }
    for (int i = t0; i < 64 * 256; i += stride) { int ic = i / 256, oc = i % 256; g_mlp1WT[i] = mlp1_w[oc * 64 + ic]; }
    for (int i = t0; i < 256 * 64; i += stride) { int ic = i / 64,  oc = i % 64;  g_mlp2WT[i] = mlp2_w[oc * 256 + ic]; }
    for (int i = t0; i < 64 * 256; i += stride) { int ic = i / 256, oc = i % 256; g_upWT[i]   = up_w[oc * 64 + ic]; }
    for (int i = t0; i < 9 * 64 * 64; i += stride) {
        int k = i >> 12, c = (i >> 6) & 63, o = i & 63;
        g_dwT[i] = deform_w[(o * 64 + c) * 9 + k];
    }
}

// ---------------- bilinear upsample (half-pixel) + channel mean + thick (NHWC out) ----------------
__global__ void upsample_kernel(const float* __restrict__ skip, const float* __restrict__ thick_w,
                                const float* __restrict__ thick_b) {
    int b = blockIdx.y, y = blockIdx.x, x = threadIdx.x;
    float sy = fminf(fmaxf(0.5f * y - 0.25f, 0.f), 31.f);
    float sx = fminf(fmaxf(0.5f * x - 0.25f, 0.f), 31.f);
    int y0 = (int)sy, x0 = (int)sx;
    int y1 = min(y0 + 1, 31), x1 = min(x0 + 1, 31);
    float wy = sy - (float)y0, wx = sx - (float)x0;
    float w00 = (1.f - wy) * (1.f - wx), w01 = (1.f - wy) * wx;
    float w10 = wy * (1.f - wx),         w11 = wy * wx;
    const float* sp = skip + (size_t)b * 64 * 1024;
    int pix = b * NPIX + y * 64 + x;
    float* up = g_skip_u + (size_t)pix * 64;
    float sum = 0.f, tsum = 0.f;
    for (int c = 0; c < 64; c++) {
        const float* p = sp + c * 1024;
        float v = w00 * p[y0 * 32 + x0] + w01 * p[y0 * 32 + x1]
                + w10 * p[y1 * 32 + x0] + w11 * p[y1 * 32 + x1];
        up[c] = v;
        sum += v;
        tsum += v * thick_w[c];
    }
    g_mean[pix] = sum * (1.f / 64.f);
    g_thick[pix] = 1.f / (1.f + expf(-(tsum + thick_b[0])));
}

// ---------------- edge conv: 3x3, 1 -> 64 ch, zero pad, no bias (NHWC out) ----------------
__global__ void edge_kernel(const float* __restrict__ edge_w) {
    int idx = blockIdx.x * 256 + threadIdx.x;          // 4*4096*64, oc fastest
    int oc = idx & 63, n = (idx >> 6) & 4095, b = idx >> 18;
    int y = n >> 6, x = n & 63;
    const float* mp = g_mean + b * NPIX;
    float a = 0.f;
#pragma unroll
    for (int ky = 0; ky < 3; ky++) {
        int yy = y + ky - 1;
        if (yy < 0 || yy >= 64) continue;
#pragma unroll
        for (int kx = 0; kx < 3; kx++) {
            int xx = x + kx - 1;
            if (xx < 0 || xx >= 64) continue;
            a += mp[yy * 64 + xx] * edge_w[oc * 9 + ky * 3 + kx];
        }
    }
    g_edge[idx] = a;
}

// ---------------- offset conv: 3x3, 64 -> 18, * (1 + 16*thick) ----------------
__global__ __launch_bounds__(512) void off_kernel(const float* __restrict__ off_w,
                                                  const float* __restrict__ off_b) {
    __shared__ float pool[64 * 9 * 18];                // ws, then reused as red[4*128*18]
    float* ws = pool;
    for (int i = threadIdx.x; i < 64 * 9 * 18; i += 512) {
        int o = i % 18, ck = i / 18;
        ws[i] = off_w[o * 576 + ck];                   // [c][k][o]
    }
    __syncthreads();
    int pl = threadIdx.x & 127, g = threadIdx.x >> 7;
    int pix = blockIdx.x * 128 + pl;
    int b = pix >> 12, n = pix & 4095;
    int y = n >> 6, x = n & 63;
    unsigned long long acc[9];
#pragma unroll
    for (int o = 0; o < 9; o++) acc[o] = 0ull;
    const float* ep = g_edge + (size_t)b * NPIX * 64;
#pragma unroll
    for (int ky = 0; ky < 3; ky++) {
        int yy = y + ky - 1;
        if (yy < 0 || yy >= 64) continue;
#pragma unroll
        for (int kx = 0; kx < 3; kx++) {
            int xx = x + kx - 1;
            if (xx < 0 || xx >= 64) continue;
            int k = ky * 3 + kx;
            const float4* col = (const float4*)(ep + (size_t)(yy * 64 + xx) * 64 + g * 16);
#pragma unroll
            for (int c4 = 0; c4 < 4; c4++) {
                float4 v4 = col[c4];
#pragma unroll
                for (int cc = 0; cc < 4; cc++) {
                    float v = (cc == 0) ? v4.x : (cc == 1) ? v4.y : (cc == 2) ? v4.z : v4.w;
                    unsigned long long vd = pack2(v, v);
                    const unsigned long long* wr =
                        (const unsigned long long*)&ws[((g * 16 + c4 * 4 + cc) * 9 + k) * 18];
#pragma unroll
                    for (int o = 0; o < 9; o++) fma2(acc[o], vd, wr[o]);
                }
            }
        }
    }
    __syncthreads();                                   // done with ws reads
    float* red = pool;                                 // [4][128][18]
#pragma unroll
    for (int o = 0; o < 9; o++)
        *(float2*)&red[((g * 128 + pl) * 18) + 2 * o] = unpack2(acc[o]);
    __syncthreads();
    for (int i = threadIdx.x; i < 128 * 18; i += 512) {
        int p2 = i / 18, o = i % 18;
        float s = red[(0 * 128 + p2) * 18 + o] + red[(1 * 128 + p2) * 18 + o]
                + red[(2 * 128 + p2) * 18 + o] + red[(3 * 128 + p2) * 18 + o];
        int gp = blockIdx.x * 128 + p2;
        float tscale = 1.f + 16.f * g_thick[gp];
        g_off[(size_t)gp * 18 + o] = (s + off_b[o]) * tscale;
    }
}

// ---------------- deformable conv 3x3 (DCNv1) + bias + edge ----------------
__global__ __launch_bounds__(64) void deform_kernel(const float* __restrict__ deform_b) {
    __shared__ float ws[4096];                         // [c][o] for current tap
    int pix = blockIdx.x * 64 + threadIdx.x;           // 16384
    int b = pix >> 12, n = pix & 4095;
    int y = n >> 6, x = n & 63;
    unsigned long long acc[32];
#pragma unroll
    for (int o = 0; o < 32; o++) acc[o] = 0ull;
    const float* su = g_skip_u + (size_t)b * NPIX * 64;
    const float* offp = g_off + (size_t)pix * 18;
    for (int k = 0; k < 9; k++) {
        __syncthreads();
        for (int i = threadIdx.x * 4; i < 4096; i += 64 * 4)
            *(float4*)&ws[i] = *(const float4*)&g_dwT[k * 4096 + i];
        __syncthreads();
        float py = (float)(y + k / 3 - 1) + offp[2 * k];
        float px = (float)(x + k % 3 - 1) + offp[2 * k + 1];
        float y0f = floorf(py), x0f = floorf(px);
        float wy = py - y0f, wx = px - x0f;
        int y0 = (int)y0f, x0 = (int)x0f;
        int y1 = y0 + 1, x1 = x0 + 1;
        bool vy0 = (y0 >= 0 && y0 < 64), vy1 = (y1 >= 0 && y1 < 64);
        bool vx0 = (x0 >= 0 && x0 < 64), vx1 = (x1 >= 0 && x1 < 64);
        float w00 = (vy0 && vx0) ? (1.f - wy) * (1.f - wx) : 0.f;
        float w01 = (vy0 && vx1) ? (1.f - wy) * wx : 0.f;
        float w10 = (vy1 && vx0) ? wy * (1.f - wx) : 0.f;
        float w11 = (vy1 && vx1) ? wy * wx : 0.f;
        int yc0 = min(max(y0, 0), 63), yc1 = min(max(y1, 0), 63);
        int xc0 = min(max(x0, 0), 63), xc1 = min(max(x1, 0), 63);
        const float4* p00 = (const float4*)(su + (size_t)(yc0 * 64 + xc0) * 64);
        const float4* p01 = (const float4*)(su + (size_t)(yc0 * 64 + xc1) * 64);
        const float4* p10 = (const float4*)(su + (size_t)(yc1 * 64 + xc0) * 64);
        const float4* p11 = (const float4*)(su + (size_t)(yc1 * 64 + xc1) * 64);
        for (int c4 = 0; c4 < 16; c4++) {
            float4 a0 = p00[c4], a1 = p01[c4], a2 = p10[c4], a3 = p11[c4];
            float4 val4;
            val4.x = w00 * a0.x + w01 * a1.x + w10 * a2.x + w11 * a3.x;
            val4.y = w00 * a0.y + w01 * a1.y + w10 * a2.y + w11 * a3.y;
            val4.z = w00 * a0.z + w01 * a1.z + w10 * a2.z + w11 * a3.z;
            val4.w = w00 * a0.w + w01 * a1.w + w10 * a2.w + w11 * a3.w;
#pragma unroll
            for (int cc = 0; cc < 4; cc++) {
                float v = (cc == 0) ? val4.x : (cc == 1) ? val4.y : (cc == 2) ? val4.z : val4.w;
                unsigned long long vd = pack2(v, v);
                const unsigned long long* wr = (const unsigned long long*)&ws[(c4 * 4 + cc) * 64];
#pragma unroll
                for (int o = 0; o < 32; o++) fma2(acc[o], vd, wr[o]);
            }
        }
    }
    const float* ep = g_edge + (size_t)pix * 64;
    float* dp = g_d + (size_t)b * 64 * NPIX + n;
#pragma unroll
    for (int o2 = 0; o2 < 32; o2++) {
        float2 a2 = unpack2(acc[o2]);
        dp[(size_t)(2 * o2 + 0) * NPIX] = a2.x + deform_b[2 * o2 + 0] + ep[2 * o2 + 0];
        dp[(size_t)(2 * o2 + 1) * NPIX] = a2.y + deform_b[2 * o2 + 1] + ep[2 * o2 + 1];
    }
}

// ---------------- 1x1-conv GEMM on tensor cores (tf32 mma.sync) ----------------
// D[oc][pix] = sum_ic WT[ic][oc] * in[ic][pix].  A = WT tile (row-major m16k8),
// B = activations (native NCHW = col-major k8n8).  Block: 256 thr = 8 warps
// (2 m x 4 n), tile 64 oc x 128 pix, K staged 16 deep.
__global__ __launch_bounds__(256) void gemm_tf32(const float* __restrict__ inA, int icA,
                                                 const float* __restrict__ inB, int IC,
                                                 const float* __restrict__ WT,
                                                 const float* __restrict__ bias, int OC,
                                                 const float* __restrict__ res,
                                                 float* __restrict__ out, int act) {
    __shared__ float Bs[16][136];
    __shared__ float Ws[16][72];
    int tid = threadIdx.x;
    int lane = tid & 31, w = tid >> 5;
    int g = lane >> 2, t = lane & 3;
    int wm = w >> 2, wn = w & 3;
    int n0 = blockIdx.x * 128;
    int oc0 = blockIdx.y * 64;
    int lb = n0 >> 12, ln = n0 & 4095;
    int icB = IC - icA;

    float acc[2][4][4];
#pragma unroll
    for (int mt = 0; mt < 2; mt++)
#pragma unroll
        for (int nt = 0; nt < 4; nt++)
#pragma unroll
            for (int j = 0; j < 4; j++) acc[mt][nt][j] = 0.f;

    int brow = tid >> 4, bcol = (tid & 15) * 8;   // B staging: 16 rows x 128
    int wrow = tid >> 4, wcol = (tid & 15) * 4;   // W staging: 16 rows x 64

    for (int k0 = 0; k0 < IC; k0 += 16) {
        __syncthreads();
        {
            int ic = k0 + brow;
            const float* src;
            if (ic < icA) src = inA + ((size_t)lb * icA + ic) * NPIX + ln + bcol;
            else          src = inB + ((size_t)lb * icB + (ic - icA)) * NPIX + ln + bcol;
            float4 v0 = *(const float4*)src;
            float4 v1 = *(const float4*)(src + 4);
            float4 s0, s1;
            s0.x = __uint_as_float(tf32_of(v0.x)); s0.y = __uint_as_float(tf32_of(v0.y));
            s0.z = __uint_as_float(tf32_of(v0.z)); s0.w = __uint_as_float(tf32_of(v0.w));
            s1.x = __uint_as_float(tf32_of(v1.x)); s1.y = __uint_as_float(tf32_of(v1.y));
            s1.z = __uint_as_float(tf32_of(v1.z)); s1.w = __uint_as_float(tf32_of(v1.w));
            *(float4*)&Bs[brow][bcol] = s0;
            *(float4*)&Bs[brow][bcol + 4] = s1;
        }
        {
            const float* wsrc = WT + (size_t)(k0 + wrow) * OC + oc0 + wcol;
            float4 wv;
            if (oc0 + wcol + 3 < OC) {
                wv = *(const float4*)wsrc;
            } else {
                wv.x = (oc0 + wcol + 0 < OC) ? wsrc[0] : 0.f;
                wv.y = (oc0 + wcol + 1 < OC) ? wsrc[1] : 0.f;
                wv.z = (oc0 + wcol + 2 < OC) ? wsrc[2] : 0.f;
                wv.w = (oc0 + wcol + 3 < OC) ? wsrc[3] : 0.f;
            }
            float4 sw;
            sw.x = __uint_as_float(tf32_of(wv.x)); sw.y = __uint_as_float(tf32_of(wv.y));
            sw.z = __uint_as_float(tf32_of(wv.z)); sw.w = __uint_as_float(tf32_of(wv.w));
            *(float4*)&Ws[wrow][wcol] = sw;
        }
        __syncthreads();
#pragma unroll
        for (int ks = 0; ks < 2; ks++) {
            int kb = ks * 8;
            unsigned af[2][4];
#pragma unroll
            for (int mt = 0; mt < 2; mt++) {
                int row = wm * 32 + mt * 16;
                af[mt][0] = __float_as_uint(Ws[kb + t][row + g]);
                af[mt][1] = __float_as_uint(Ws[kb + t][row + g + 8]);
                af[mt][2] = __float_as_uint(Ws[kb + t + 4][row + g]);
                af[mt][3] = __float_as_uint(Ws[kb + t + 4][row + g + 8]);
            }
#pragma unroll
            for (int nt = 0; nt < 4; nt++) {
                int col = wn * 32 + nt * 8 + g;
                unsigned b0 = __float_as_uint(Bs[kb + t][col]);
                unsigned b1 = __float_as_uint(Bs[kb + t + 4][col]);
                mma_tf32(acc[0][nt], af[0], b0, b1);
                mma_tf32(acc[1][nt], af[1], b0, b1);
            }
        }
    }
#pragma unroll
    for (int mt = 0; mt < 2; mt++) {
#pragma unroll
        for (int nt = 0; nt < 4; nt++) {
            int col = ln + wn * 32 + nt * 8 + 2 * t;
#pragma unroll
            for (int r = 0; r < 2; r++) {
                int oc = oc0 + wm * 32 + mt * 16 + g + r * 8;
                if (oc < OC) {
                    float v0 = acc[mt][nt][r * 2 + 0] + bias[oc];
                    float v1 = acc[mt][nt][r * 2 + 1] + bias[oc];
                    if (act) { v0 = v0 * normcdff(v0); v1 = v1 * normcdff(v1); }
                    size_t oi = ((size_t)lb * OC + oc) * NPIX + col;
                    if (res) { v0 += res[oi]; v1 += res[oi + 1]; }
                    *(float2*)&out[oi] = make_float2(v0, v1);
                }
            }
        }
    }
}

// ---------------- flash attention (tf32 mma.sync): N=4096, d=32 per batch ----------------
__global__ __launch_bounds__(128) void flash_kernel() {
    __shared__ float Kt_s[32 * 72];        // [ch][key], stride 72 (conflict-free frags)
    __shared__ float Vs_s[64 * 41];        // [key][ch], stride 41
    __shared__ float Ps_s[4 * 16 * 72];    // per-warp P tile [q][key], stride 72
    int b = blockIdx.y;
    int q0 = blockIdx.x * 64;
    int tid = threadIdx.x;
    int w = tid >> 5, lane = tid & 31;
    int g = lane >> 2, t = lane & 3;
    const float* qkv = g_qkv + (size_t)b * 96 * NPIX;
    const float QSCALE = 1.4426950408889634f * 0.17677669529663687f;  // log2(e)/sqrt(32)
    int qrow = q0 + w * 16 + g;

    unsigned qa[4][4];
#pragma unroll
    for (int kc = 0; kc < 4; kc++) {
        qa[kc][0] = tf32_of(qkv[(size_t)(kc * 8 + t) * NPIX + qrow] * QSCALE);
        qa[kc][1] = tf32_of(qkv[(size_t)(kc * 8 + t) * NPIX + qrow + 8] * QSCALE);
        qa[kc][2] = tf32_of(qkv[(size_t)(kc * 8 + t + 4) * NPIX + qrow] * QSCALE);
        qa[kc][3] = tf32_of(qkv[(size_t)(kc * 8 + t + 4) * NPIX + qrow + 8] * QSCALE);
    }

    float m0 = -INFINITY, m1 = -INFINITY, l0 = 0.f, l1 = 0.f;
    float o[4][4];
#pragma unroll
    for (int i = 0; i < 4; i++)
#pragma unroll
        for (int j = 0; j < 4; j++) o[i][j] = 0.f;
    float* Pw = Ps_s + w * 16 * 72;

    for (int kt = 0; kt < 64; kt++) {
        int k0 = kt * 64;
        __syncthreads();
        for (int i = tid; i < 2048; i += 128) {
            int ch = i >> 6, key = i & 63;
            Kt_s[ch * 72 + key] = __uint_as_float(tf32_of(qkv[(size_t)(32 + ch) * NPIX + k0 + key]));
            Vs_s[key * 41 + ch] = __uint_as_float(tf32_of(qkv[(size_t)(64 + ch) * NPIX + k0 + key]));
        }
        __syncthreads();

        float s[8][4];
#pragma unroll
        for (int nt = 0; nt < 8; nt++)
#pragma unroll
            for (int j = 0; j < 4; j++) s[nt][j] = 0.f;
#pragma unroll
        for (int nt = 0; nt < 8; nt++) {
#pragma unroll
            for (int kc = 0; kc < 4; kc++) {
                unsigned b0 = __float_as_uint(Kt_s[(kc * 8 + t) * 72 + nt * 8 + g]);
                unsigned b1 = __float_as_uint(Kt_s[(kc * 8 + t + 4) * 72 + nt * 8 + g]);
                mma_tf32(s[nt], qa[kc], b0, b1);
            }
        }

        float pm0 = -INFINITY, pm1 = -INFINITY;
#pragma unroll
        for (int nt = 0; nt < 8; nt++) {
            pm0 = fmaxf(pm0, fmaxf(s[nt][0], s[nt][1]));
            pm1 = fmaxf(pm1, fmaxf(s[nt][2], s[nt][3]));
        }
        pm0 = fmaxf(pm0, __shfl_xor_sync(0xffffffffu, pm0, 1, 4));
        pm0 = fmaxf(pm0, __shfl_xor_sync(0xffffffffu, pm0, 2, 4));
        pm1 = fmaxf(pm1, __shfl_xor_sync(0xffffffffu, pm1, 1, 4));
        pm1 = fmaxf(pm1, __shfl_xor_sync(0xffffffffu, pm1, 2, 4));
        float mn0 = fmaxf(m0, pm0), mn1 = fmaxf(m1, pm1);
        float al0 = exp2f(m0 - mn0), al1 = exp2f(m1 - mn1);
        m0 = mn0; m1 = mn1;
        l0 *= al0; l1 *= al1;
#pragma unroll
        for (int c = 0; c < 4; c++) {
            o[c][0] *= al0; o[c][1] *= al0;
            o[c][2] *= al1; o[c][3] *= al1;
        }
        float ps0 = 0.f, ps1 = 0.f;
#pragma unroll
        for (int nt = 0; nt < 8; nt++) {
            float p0 = exp2f(s[nt][0] - mn0);
            float p1 = exp2f(s[nt][1] - mn0);
            float p2 = exp2f(s[nt][2] - mn1);
            float p3 = exp2f(s[nt][3] - mn1);
            ps0 += p0 + p1; ps1 += p2 + p3;
            uint2 lo = make_uint2(tf32_of(p0), tf32_of(p1));
            uint2 hi = make_uint2(tf32_of(p2), tf32_of(p3));
            *(uint2*)&Pw[g * 72 + nt * 8 + 2 * t] = lo;
            *(uint2*)&Pw[(g + 8) * 72 + nt * 8 + 2 * t] = hi;
        }
        ps0 += __shfl_xor_sync(0xffffffffu, ps0, 1, 4);
        ps0 += __shfl_xor_sync(0xffffffffu, ps0, 2, 4);
        ps1 += __shfl_xor_sync(0xffffffffu, ps1, 1, 4);
        ps1 += __shfl_xor_sync(0xffffffffu, ps1, 2, 4);
        l0 += ps0; l1 += ps1;
        __syncwarp();

#pragma unroll
        for (int c = 0; c < 8; c++) {
            unsigned pa[4];
            pa[0] = __float_as_uint(Pw[g * 72 + c * 8 + t]);
            pa[1] = __float_as_uint(Pw[(g + 8) * 72 + c * 8 + t]);
            pa[2] = __float_as_uint(Pw[g * 72 + c * 8 + t + 4]);
            pa[3] = __float_as_uint(Pw[(g + 8) * 72 + c * 8 + t + 4]);
#pragma unroll
            for (int nt2 = 0; nt2 < 4; nt2++) {
                unsigned b0 = __float_as_uint(Vs_s[(c * 8 + t) * 41 + nt2 * 8 + g]);
                unsigned b1 = __float_as_uint(Vs_s[(c * 8 + t + 4) * 41 + nt2 * 8 + g]);
                mma_tf32(o[nt2], pa, b0, b1);
            }
        }
        __syncwarp();
    }

    float inv0 = 1.f / l0, inv1 = 1.f / l1;
    float* av = g_av + (size_t)b * 32 * NPIX;
#pragma unroll
    for (int nt2 = 0; nt2 < 4; nt2++) {
        int ch = nt2 * 8 + 2 * t;
        av[(size_t)ch * NPIX + qrow]           = o[nt2][0] * inv0;
        av[(size_t)(ch + 1) * NPIX + qrow]     = o[nt2][1] * inv0;
        av[(size_t)ch * NPIX + qrow + 8]       = o[nt2][2] * inv1;
        av[(size_t)(ch + 1) * NPIX + qrow + 8] = o[nt2][3] * inv1;
    }
}

// ---------------- layernorm over 64 channels per pixel ----------------
__global__ void ln_kernel(const float* __restrict__ ln_g, const float* __restrict__ ln_b) {
    int p = blockIdx.x * 256 + threadIdx.x;
    int b = p >> 12, n = p & 4095;
    const float* ep = g_e + (size_t)b * 64 * NPIX + n;
    float v[64], mu = 0.f;
#pragma unroll
    for (int c = 0; c < 64; c++) { v[c] = ep[(size_t)c * NPIX]; mu += v[c]; }
    mu *= (1.f / 64.f);
    float var = 0.f;
#pragma unroll
    for (int c = 0; c < 64; c++) { float d = v[c] - mu; var += d * d; }
    var *= (1.f / 64.f);
    float inv = rsqrtf(var + 1e-5f);
    float* hp = g_h + (size_t)b * 64 * NPIX + n;
#pragma unroll
    for (int c = 0; c < 64; c++) hp[(size_t)c * NPIX] = (v[c] - mu) * inv * ln_g[c] + ln_b[c];
}

// ---------------- depthwise 3x3 conv + bias + GELU ----------------
__global__ void dw_kernel(const float* __restrict__ dw_w, const float* __restrict__ dw_b) {
    int idx = blockIdx.x * 256 + threadIdx.x;          // 4*256*4096
    int n = idx & 4095, c = (idx >> 12) & 255;
    int y = n >> 6, x = n & 63;
    const float* hp = g_h1 + (size_t)(idx >> 12) * NPIX;
    const float* w = dw_w + c * 9;
    float a = 0.f;
#pragma unroll
    for (int ky = 0; ky < 3; ky++) {
        int yy = y + ky - 1;
        if (yy < 0 || yy >= 64) continue;
#pragma unroll
        for (int kx = 0; kx < 3; kx++) {
            int xx = x + kx - 1;
            if (xx < 0 || xx >= 64) continue;
            a += hp[yy * 64 + xx] * w[ky * 3 + kx];
        }
    }
    a += dw_b[c];
    g_h2[idx] = a * normcdff(a);
}

// ---------------- host launcher ----------------
extern "C" void kernel_launch(void* const* d_in, const int* in_sizes, int n_in,
                              void* d_out, int out_size) {
    (void)in_sizes; (void)n_in; (void)out_size;
    const float* x       = (const float*)d_in[0];
    const float* skip    = (const float*)d_in[1];
    const float* qkv_w   = (const float*)d_in[2];
    const float* qkv_b   = (const float*)d_in[3];
    const float* proj_w  = (const float*)d_in[4];
    const float* proj_b  = (const float*)d_in[5];
    const float* edge_w  = (const float*)d_in[6];
    const float* thick_w = (const float*)d_in[7];
    const float* thick_b = (const float*)d_in[8];
    const float* off_w   = (const float*)d_in[9];
    const float* off_b   = (const float*)d_in[10];
    const float* deform_w= (const float*)d_in[11];
    const float* deform_b= (const float*)d_in[12];
    const float* ln_g    = (const float*)d_in[13];
    const float* ln_b    = (const float*)d_in[14];
    const float* mlp1_w  = (const float*)d_in[15];
    const float* mlp1_b  = (const float*)d_in[16];
    const float* dw_w    = (const float*)d_in[17];
    const float* dw_b    = (const float*)d_in[18];
    const float* mlp2_w  = (const float*)d_in[19];
    const float* mlp2_b  = (const float*)d_in[20];
    const float* down_w  = (const float*)d_in[21];
    const float* down_b  = (const float*)d_in[22];
    const float* up_w    = (const float*)d_in[23];
    const float* up_b    = (const float*)d_in[24];
    float* out = (float*)d_out;

    float *p_qkv, *p_av, *p_x2, *p_d, *p_e, *p_h, *p_h1, *p_h2, *p_t;
    float *p_qkvWT, *p_projWT, *p_downWT, *p_mlp1WT, *p_mlp2WT, *p_upWT;
    cudaGetSymbolAddress((void**)&p_qkv,    g_qkv);
    cudaGetSymbolAddress((void**)&p_av,     g_av);
    cudaGetSymbolAddress((void**)&p_x2,     g_x2);
    cudaGetSymbolAddress((void**)&p_d,      g_d);
    cudaGetSymbolAddress((void**)&p_e,      g_e);
    cudaGetSymbolAddress((void**)&p_h,      g_h);
    cudaGetSymbolAddress((void**)&p_h1,     g_h1);
    cudaGetSymbolAddress((void**)&p_h2,     g_h2);
    cudaGetSymbolAddress((void**)&p_t,      g_t);
    cudaGetSymbolAddress((void**)&p_qkvWT,  g_qkvWT);
    cudaGetSymbolAddress((void**)&p_projWT, g_projWT);
    cudaGetSymbolAddress((void**)&p_downWT, g_downWT);
    cudaGetSymbolAddress((void**)&p_mlp1WT, g_mlp1WT);
    cudaGetSymbolAddress((void**)&p_mlp2WT, g_mlp2WT);
    cudaGetSymbolAddress((void**)&p_upWT,   g_upWT);

    prep_kernel<<<128, 256>>>(qkv_w, proj_w, down_w, mlp1_w, mlp2_w, up_w, deform_w);
    upsample_kernel<<<dim3(64, 4), 64>>>(skip, thick_w, thick_b);
    edge_kernel<<<4096, 256>>>(edge_w);
    off_kernel<<<128, 512>>>(off_w, off_b);
    deform_kernel<<<256, 64>>>(deform_b);

    // qkv = conv1x1(x) ; flash attention (tf32) ; proj + residual x
    gemm_tf32<<<dim3(128, 2), 256>>>(x, 256, nullptr, 256, p_qkvWT, qkv_b, 96, nullptr, p_qkv, 0);
    flash_kernel<<<dim3(64, 4), 128>>>();
    gemm_tf32<<<dim3(128, 4), 256>>>(p_av, 32, nullptr, 32, p_projWT, proj_b, 256, x, p_x2, 0);

    // down(concat[x2, d]) -> LN -> mlp1+gelu -> dw+gelu -> mlp2 + e -> up
    gemm_tf32<<<dim3(128, 1), 256>>>(p_x2, 256, p_d, 320, p_downWT, down_b, 64, nullptr, p_e, 0);
    ln_kernel<<<64, 256>>>(ln_g, ln_b);
    gemm_tf32<<<dim3(128, 4), 256>>>(p_h, 64, nullptr, 64, p_mlp1WT, mlp1_b, 256, nullptr, p_h1, 1);
    dw_kernel<<<16384, 256>>>(dw_w, dw_b);
    gemm_tf32<<<dim3(128, 1), 256>>>(p_h2, 256, nullptr, 256, p_mlp2WT, mlp2_b, 64, p_e, p_t, 0);
    gemm_tf32<<<dim3(128, 4), 256>>>(p_t, 64, nullptr, 64, p_upWT, up_b, 256, nullptr, out, 0);
}